// round 12
// baseline (speedup 1.0000x reference)
#include <cuda_runtime.h>
#include <cuda_bf16.h>
#include <mma.h>
#include <math.h>
#include <stdint.h>
using namespace nvcuda;

// ---------------- problem constants ----------------
#define BB   64      // batch
#define TSR  64      // src len
#define TTR  64      // trg len
#define EE   512     // embedding
#define HH   512     // encoder hidden per dir
#define DDH  1024    // decoder hidden
#define VOC  32000
#define TD   63              // decode steps
#define MR   (TD*BB)         // 4032 rows
#define MRP  4096            // padded row count for 128-tiles
#define NTV  (VOC/128)       // 250 column tiles of vocab
#define NBE  32              // encoder persistent grid
#define NBD  256             // decoder persistent grid

#define AS_STAGE (64*72)
#define WS_STAGE (128*72)
#define DYN_SMEM ((2*AS_STAGE + 2*WS_STAGE) * 2)   // 55296 bytes (64x128 core)

#define G128_STAGE (128*72)                         // bf16 elems per tensor per stage
#define DYN2 (4*G128_STAGE*2)                       // 73728 bytes (128x128 core)

typedef __nv_bfloat16 bf16;
typedef __nv_bfloat162 bf162;

// ---------------- static device scratch ----------------
__device__ bf16 g_svb  [BB*TSR*EE];       // src embedded bf16, row = b*TSR+t
__device__ bf16 g_tvb  [MRP*EE];          // trg embedded bf16, row = t*BB+b (padded)
__device__ bf16 g_WencfP[4*HH*EE];        // enc_Wih bf16, gate-interleaved rows
__device__ bf16 g_WencrP[4*HH*EE];
__device__ bf16 g_WhhfP [4*HH*HH];        // enc_Whh bf16 interleaved
__device__ bf16 g_WhhrP [4*HH*HH];
__device__ bf16 g_WdecE [4*DDH*EE];       // dec_Wih[:, :512] interleaved
__device__ bf16 g_WdecR [4*DDH*2048];     // [dec_Wih[:,512:1536] | dec_Whh] interleaved
__device__ bf16 g_WhidB [DDH*2*DDH];      // hid_W bf16 plain [1024][2048]
__device__ bf16 g_WhidLT[DDH*DDH];        // hid_W left half transposed  [k][j]
__device__ bf16 g_WhidRT[DDH*DDH];        // hid_W right half transposed [k][j]
__device__ bf16 g_Wgate [4*DDH*DDH];      // WA@WhidL + Whh (interleaved rows)
__device__ bf16 g_WcombC[4*DDH*DDH];      // WA@WhidR (interleaved rows)
__device__ bf16 g_HencC [BB*TSR*4*DDH];   // Henc @ WcombC^T  [(b*64+u)][4096]
__device__ bf16 g_Wout  [VOC*DDH];        // out_W bf16 plain
__device__ bf16 g_avallb[MRP*DDH];        // all av rows bf16 (padded)
__device__ bf16 g_yall  [MRP*2048];       // [h|ctx] rows (padded)

__device__ float g_bencfP[4*HH];          // permuted biases (fp32)
__device__ float g_bencrP[4*HH];
__device__ float g_bdecP [4*DDH];
__device__ float g_constA[4*DDH];         // WA_P @ hid_b

__device__ float g_Gf   [BB*TSR*4*HH];    // enc fwd preact (interleaved cols)
__device__ float g_Gr   [BB*TSR*4*HH];
__device__ float g_Gdec [MRP*4*DDH];      // dec preact (emb part + bias, interleaved)
__device__ float g_Henc [BB*TSR*2*HH];    // fp32 (for final-state gather)
__device__ float g_Cenc [BB*TSR*2*HH];
__device__ bf16  g_Hencb[BB*TSR*2*HH];    // bf16 copy for attention / HencC GEMM
__device__ bf16  g_hsb  [2*BB*HH];        // enc running h bf16 (both dirs)
__device__ float g_cs   [2*BB*HH];        // enc running c fp32
__device__ float g_c    [BB*DDH];         // dec c fp32
__device__ bf16  g_hb   [BB*DDH];         // dec h bf16 (gates GEMM input)
__device__ float g_ctxg [BB*4*DDH];       // ctx-contribution to next gates (fp32)
__device__ float g_spg  [BB*64];          // softmax probs (global, for ctxg blocks)
__device__ float g_Pg   [4*BB*4*DDH];     // gates split-K partials (4 x [64,4096])
__device__ float g_Phid [4*BB*DDH];       // init-GEMM split-K partials
__device__ float g_final[BB*2*DDH];       // concat(Henc,Cenc) at last
__device__ float g_chunk[MR*NTV*2];       // per-tile (max, sumexp)
__device__ float g_gold [MR];
__device__ int   g_goldtok[MR];
__device__ float g_maskf[MR];
__device__ float g_rowval[MR];
__device__ unsigned g_bar[8];             // encoder barrier: [0]=cnt [1]=gen
__device__ unsigned g_bar2[16];           // decoder barrier: [0..7]=sub [8]=master [9]=gen

__device__ __forceinline__ float sigf(float x) { return 1.0f / (1.0f + expf(-x)); }
__device__ __forceinline__ bf162 cvt2(float a, float b) {
    return __float22bfloat162_rn(make_float2(a, b));
}
__device__ __forceinline__ uint32_t smem_u32(const void* p) {
    uint32_t a;
    asm("{ .reg .u64 t; cvta.to.shared.u64 t, %1; cvt.u32.u64 %0, t; }" : "=r"(a) : "l"(p));
    return a;
}
__device__ __forceinline__ void cp16(uint32_t dst, const void* src) {
    asm volatile("cp.async.cg.shared.global [%0], [%1], 16;" :: "r"(dst), "l"(src));
}
__device__ __forceinline__ void cp_commit() { asm volatile("cp.async.commit_group;"); }
__device__ __forceinline__ void cp_wait0() { asm volatile("cp.async.wait_group 0;" ::: "memory"); }

// ---------------- device-wide barriers ----------------
// simple barrier (encoder, 32 blocks)
__device__ __forceinline__ void gsync(unsigned nb, unsigned& mygen) {
    __threadfence();
    __syncthreads();
    if (threadIdx.x == 0) {
        unsigned g = mygen;
        if (atomicAdd(&g_bar[0], 1u) == nb - 1u) {
            atomicExch(&g_bar[0], 0u);
            __threadfence();
            atomicExch(&g_bar[1], g + 1u);
        } else {
            volatile unsigned* vg = (volatile unsigned*)&g_bar[1];
            while (*vg == g) __nanosleep(64);
        }
    }
    mygen++;
    __syncthreads();
}

// hierarchical barrier (decoder, NBD blocks, NBD % 8 == 0)
__device__ __forceinline__ void gsyncH(unsigned nb, unsigned& mygen) {
    __threadfence();
    __syncthreads();
    if (threadIdx.x == 0) {
        unsigned g = mygen;
        unsigned sub = blockIdx.x & 7u;
        unsigned quota = nb >> 3;
        bool done = false;
        if (atomicAdd(&g_bar2[sub], 1u) == quota - 1u) {
            if (atomicAdd(&g_bar2[8], 1u) == 7u) {
#pragma unroll
                for (int i = 0; i < 8; i++) atomicExch(&g_bar2[i], 0u);
                atomicExch(&g_bar2[8], 0u);
                __threadfence();
                atomicExch(&g_bar2[9], g + 1u);
                done = true;
            }
        }
        if (!done) {
            volatile unsigned* vg = (volatile unsigned*)&g_bar2[9];
            while (*vg == g) __nanosleep(64);
        }
    }
    mygen++;
    __syncthreads();
}

// ============ 64x128 GEMM core (persistent kernels), K-tile 64, cp.async ============
__device__ __forceinline__ void gemm_core(
    const bf16* __restrict__ A, int lda,
    const bf16* __restrict__ W, int ldw,
    int K, char* smem, float* out, int ldo)
{
    bf16* As = (bf16*)smem;                  // 2 stages x 64 x 72
    bf16* Ws = (bf16*)smem + 2 * AS_STAGE;   // 2 stages x 128 x 72
    int tid = threadIdx.x;
    int wid = tid >> 5;
    int wr = (wid & 1) * 32, wc = (wid >> 1) * 32;

    wmma::fragment<wmma::accumulator, 16, 16, 16, float> acc[2][2];
#pragma unroll
    for (int i = 0; i < 2; i++)
#pragma unroll
        for (int j = 0; j < 2; j++) wmma::fill_fragment(acc[i][j], 0.f);

    int ar = tid >> 2, ac = (tid & 3) * 16;   // A: 64 rows x 4 chunks of 16 (32B)
    int wq = tid >> 1, wz = (tid & 1) * 32;   // W: 128 rows x 2 chunks of 32 (64B)
    const bf16* Ap = A + (size_t)ar * lda + ac;
    const bf16* Wp = W + (size_t)wq * ldw + wz;
    uint32_t sA = smem_u32(As) + ((uint32_t)ar * 72u + (uint32_t)ac) * 2u;
    uint32_t sW = smem_u32(Ws) + ((uint32_t)wq * 72u + (uint32_t)wz) * 2u;
    const uint32_t stA = AS_STAGE * 2u, stW = WS_STAGE * 2u;

    // prologue: stage 0
    cp16(sA, Ap); cp16(sA + 16, Ap + 8);
    cp16(sW, Wp); cp16(sW + 16, Wp + 8);
    cp16(sW + 32, Wp + 16); cp16(sW + 48, Wp + 24);
    cp_commit();

    int niter = K >> 6;
    int cur = 0;
    for (int it = 0; it < niter; ++it) {
        cp_wait0();
        __syncthreads();
        if (it + 1 < niter) {
            const bf16* a = Ap + (it + 1) * 64;
            const bf16* w = Wp + (it + 1) * 64;
            uint32_t da = sA + (uint32_t)((it + 1) & 1) * stA;
            uint32_t dw = sW + (uint32_t)((it + 1) & 1) * stW;
            cp16(da, a); cp16(da + 16, a + 8);
            cp16(dw, w); cp16(dw + 16, w + 8);
            cp16(dw + 32, w + 16); cp16(dw + 48, w + 24);
            cp_commit();
        }
        const bf16* Ab = As + cur * AS_STAGE;
        const bf16* Wb = Ws + cur * WS_STAGE;
#pragma unroll
        for (int kk = 0; kk < 64; kk += 16) {
            wmma::fragment<wmma::matrix_a, 16, 16, 16, bf16, wmma::row_major> af[2];
            wmma::fragment<wmma::matrix_b, 16, 16, 16, bf16, wmma::col_major> bfr[2];
            wmma::load_matrix_sync(af[0], Ab + wr * 72 + kk, 72);
            wmma::load_matrix_sync(af[1], Ab + (wr + 16) * 72 + kk, 72);
            wmma::load_matrix_sync(bfr[0], Wb + wc * 72 + kk, 72);
            wmma::load_matrix_sync(bfr[1], Wb + (wc + 16) * 72 + kk, 72);
#pragma unroll
            for (int i = 0; i < 2; i++)
#pragma unroll
                for (int j = 0; j < 2; j++)
                    wmma::mma_sync(acc[i][j], af[i], bfr[j], acc[i][j]);
        }
        cur ^= 1;
    }
    __syncthreads();
#pragma unroll
    for (int i = 0; i < 2; i++)
#pragma unroll
        for (int j = 0; j < 2; j++)
            wmma::store_matrix_sync(out + (size_t)(wr + i * 16) * ldo + wc + j * 16,
                                    acc[i][j], ldo, wmma::mem_row_major);
    __syncthreads();
}

// ============ 128x128 GEMM core (feed-forward), warp tile 32x64, cp.async ============
__device__ __forceinline__ void gemm128(
    const bf16* __restrict__ A, int lda,
    const bf16* __restrict__ W, int ldw,
    int K, char* smem, float* out, int ldo)
{
    bf16* As = (bf16*)smem;                     // 2 stages x 128 x 72
    bf16* Ws = (bf16*)smem + 2 * G128_STAGE;    // 2 stages x 128 x 72
    int tid = threadIdx.x;
    int wid = tid >> 5;
    int wm = (wid & 3) * 32, wn = (wid >> 2) * 64;

    wmma::fragment<wmma::accumulator, 16, 16, 16, float> acc[2][4];
#pragma unroll
    for (int i = 0; i < 2; i++)
#pragma unroll
        for (int j = 0; j < 4; j++) wmma::fill_fragment(acc[i][j], 0.f);

    int r = tid >> 1, hc = (tid & 1) * 32;      // 128 rows x 2 half-rows of 32 (64B)
    const bf16* Ap = A + (size_t)r * lda + hc;
    const bf16* Wp = W + (size_t)r * ldw + hc;
    uint32_t sA = smem_u32(As) + ((uint32_t)r * 72u + (uint32_t)hc) * 2u;
    uint32_t sW = smem_u32(Ws) + ((uint32_t)r * 72u + (uint32_t)hc) * 2u;
    const uint32_t stB = G128_STAGE * 2u;

    // prologue: stage 0
    cp16(sA, Ap); cp16(sA + 16, Ap + 8); cp16(sA + 32, Ap + 16); cp16(sA + 48, Ap + 24);
    cp16(sW, Wp); cp16(sW + 16, Wp + 8); cp16(sW + 32, Wp + 16); cp16(sW + 48, Wp + 24);
    cp_commit();

    int niter = K >> 6;
    int cur = 0;
    for (int it = 0; it < niter; ++it) {
        cp_wait0();
        __syncthreads();
        if (it + 1 < niter) {
            const bf16* a = Ap + (it + 1) * 64;
            const bf16* w = Wp + (it + 1) * 64;
            uint32_t off = (uint32_t)((it + 1) & 1) * stB;
            uint32_t da = sA + off, dw = sW + off;
            cp16(da, a); cp16(da + 16, a + 8); cp16(da + 32, a + 16); cp16(da + 48, a + 24);
            cp16(dw, w); cp16(dw + 16, w + 8); cp16(dw + 32, w + 16); cp16(dw + 48, w + 24);
            cp_commit();
        }
        const bf16* Ab = As + cur * G128_STAGE;
        const bf16* Wb = Ws + cur * G128_STAGE;
#pragma unroll
        for (int kk = 0; kk < 64; kk += 16) {
            wmma::fragment<wmma::matrix_a, 16, 16, 16, bf16, wmma::row_major> af[2];
            wmma::fragment<wmma::matrix_b, 16, 16, 16, bf16, wmma::col_major> bfr[4];
            wmma::load_matrix_sync(af[0], Ab + wm * 72 + kk, 72);
            wmma::load_matrix_sync(af[1], Ab + (wm + 16) * 72 + kk, 72);
#pragma unroll
            for (int j = 0; j < 4; j++)
                wmma::load_matrix_sync(bfr[j], Wb + (wn + j * 16) * 72 + kk, 72);
#pragma unroll
            for (int i = 0; i < 2; i++)
#pragma unroll
                for (int j = 0; j < 4; j++)
                    wmma::mma_sync(acc[i][j], af[i], bfr[j], acc[i][j]);
        }
        cur ^= 1;
    }
    __syncthreads();
#pragma unroll
    for (int i = 0; i < 2; i++)
#pragma unroll
        for (int j = 0; j < 4; j++)
            wmma::store_matrix_sync(out + (size_t)(wm + i * 16) * ldo + wn + j * 16,
                                    acc[i][j], ldo, wmma::mem_row_major);
    __syncthreads();
}

// ---------------- conversions / permutations ----------------
__global__ void k_f2b(const float* __restrict__ x, bf16* __restrict__ y, int n4) {
    int i = blockIdx.x * blockDim.x + threadIdx.x;
    if (i < n4) {
        float4 v = ((const float4*)x)[i];
        ((bf162*)y)[2 * i]     = cvt2(v.x, v.y);
        ((bf162*)y)[2 * i + 1] = cvt2(v.z, v.w);
    }
}

__global__ void k_permW512(const float* __restrict__ W, bf16* __restrict__ out,
                           int J, int ldin) {
    int row = blockIdx.x;
    int j = row >> 2, g = row & 3;
    const float4* src = (const float4*)(W + (size_t)(g * J + j) * ldin);
    bf162* dst = (bf162*)(out + (size_t)row * 512);
    int t = threadIdx.x;                   // 128
    float4 v = src[t];
    dst[2 * t]     = cvt2(v.x, v.y);
    dst[2 * t + 1] = cvt2(v.z, v.w);
}

__global__ void k_permDecR(const float* __restrict__ Wih, const float* __restrict__ Whh) {
    int row = blockIdx.x;                  // 4096
    int j = row >> 2, g = row & 3;
    int t = threadIdx.x;                   // 256, 8 elems each
    const float* src = (t < 128)
        ? (Wih + (size_t)(g * 1024 + j) * 1536 + 512 + t * 8)
        : (Whh + (size_t)(g * 1024 + j) * 1024 + (t - 128) * 8);
    bf162* dst = (bf162*)(g_WdecR + (size_t)row * 2048 + t * 8);
    float4 a = *(const float4*)src;
    float4 b = *(const float4*)(src + 4);
    dst[0] = cvt2(a.x, a.y); dst[1] = cvt2(a.z, a.w);
    dst[2] = cvt2(b.x, b.y); dst[3] = cvt2(b.z, b.w);
}

__global__ void k_permB(const float* __restrict__ b, float* __restrict__ out, int J) {
    int i = blockIdx.x * blockDim.x + threadIdx.x;
    if (i < 4 * J) { int j = i >> 2, g = i & 3; out[i] = b[g * J + j]; }
}

// transpose hid_W halves -> bf16 [k][j]
__global__ void k_transpose_hid(const float* __restrict__ W) {
    __shared__ float tile[32][33];
    int half = blockIdx.z;
    int k0 = blockIdx.x * 32;
    int j0 = blockIdx.y * 32;
    int tx = threadIdx.x, ty = threadIdx.y;   // 32 x 8
#pragma unroll
    for (int i = 0; i < 32; i += 8)
        tile[ty + i][tx] = W[(size_t)(j0 + ty + i) * 2048 + half * 1024 + k0 + tx];
    __syncthreads();
    bf16* out = half ? g_WhidRT : g_WhidLT;
#pragma unroll
    for (int i = 0; i < 32; i += 8)
        out[(size_t)(k0 + ty + i) * 1024 + j0 + tx] = __float2bfloat16(tile[tx][ty + i]);
}

// constA[row] = dot(WA_P[row,:], hid_b)
__global__ void k_const(const float* __restrict__ hid_b) {
    int row = blockIdx.x * 8 + (threadIdx.x >> 5);
    int lane = threadIdx.x & 31;
    const bf16* wr = g_WdecR + (size_t)row * 2048;
    float s = 0.f;
    for (int k = lane; k < 1024; k += 32) s += __bfloat162float(wr[k]) * hid_b[k];
#pragma unroll
    for (int o = 16; o > 0; o >>= 1) s += __shfl_xor_sync(0xffffffffu, s, o);
    if (lane == 0) g_constA[row] = s;
}

// ---------------- init / gathers ----------------
__global__ void k_zero_state() {
    int i = blockIdx.x * blockDim.x + threadIdx.x;
    if (i < 2 * BB * HH) { g_cs[i] = 0.f; g_hsb[i] = __float2bfloat16(0.f); }
    if (i < 8) g_bar[i] = 0u;
    if (i < 16) g_bar2[i] = 0u;
}

// zero the pad rows (rows MR..MRP) of avall / tvb / yall
__global__ void k_zeropad() {
    int i = blockIdx.x * blockDim.x + threadIdx.x;
    bf16 z = __float2bfloat16(0.f);
    if (i < 64 * 1024) g_avallb[MR * DDH + i] = z;
    if (i < 64 * 512)  g_tvb[MR * EE + i] = z;
    if (i < 64 * 2048) g_yall[(size_t)MR * 2048 + i] = z;
}

__global__ void k_gather_src(const int* __restrict__ tok, const float* __restrict__ emb) {
    int r = blockIdx.x;
    int v = tok[r];
    float4 val = ((const float4*)(emb + (size_t)v * EE))[threadIdx.x];
    bf162* d = (bf162*)(g_svb + (size_t)r * EE + threadIdx.x * 4);
    d[0] = cvt2(val.x, val.y); d[1] = cvt2(val.z, val.w);
}

__global__ void k_gather_trg(const int* __restrict__ tok, const int* __restrict__ lens,
                             const float* __restrict__ emb) {
    int r = blockIdx.x;                    // t*BB + b
    int t = r >> 6, b = r & 63;
    int v = tok[b * TTR + t];
    float4 val = ((const float4*)(emb + (size_t)v * EE))[threadIdx.x];
    bf162* d = (bf162*)(g_tvb + (size_t)r * EE + threadIdx.x * 4);
    d[0] = cvt2(val.x, val.y); d[1] = cvt2(val.z, val.w);
    if (threadIdx.x == 0) {
        g_goldtok[r] = tok[b * TTR + t + 1];
        g_maskf[r] = ((t + 1) < lens[b]) ? 1.0f : 0.0f;
    }
}

// ---------------- 128-tile feed-forward GEMM (fp32 out): C = A @ W^T + bias ----------------
__global__ __launch_bounds__(256) void k_ff128(
    const bf16* __restrict__ A, int lda,
    const bf16* __restrict__ W, int ldw,
    const float* __restrict__ bias,
    float* __restrict__ C, int ldc, int K)
{
    extern __shared__ __align__(16) char dyn[];
    float* Cs = (float*)dyn;
    int m0 = blockIdx.x * 128, n0 = blockIdx.y * 128;
    gemm128(A + (size_t)m0 * lda, lda, W + (size_t)n0 * ldw, ldw, K, dyn, Cs, 136);
    int tid = threadIdx.x;
    for (int e = tid; e < 4096; e += 256) {
        int r = e >> 5, c4 = (e & 31) * 4;
        float4 v = *(const float4*)(Cs + r * 136 + c4);
        float4 bv = *(const float4*)(bias + n0 + c4);
        v.x += bv.x; v.y += bv.y; v.z += bv.z; v.w += bv.w;
        *(float4*)(C + (size_t)(m0 + r) * ldc + n0 + c4) = v;
    }
}

// ---------------- 128-tile GEMM (bf16 out, optional bias / bf16 add) ----------------
__global__ __launch_bounds__(256) void k_gemm128_b(
    const bf16* __restrict__ A, int lda,
    const bf16* __restrict__ W, int ldw, int K,
    const float* __restrict__ bias,
    const bf16* __restrict__ addW, int ldadd,
    bf16* __restrict__ out, int ldo)
{
    extern __shared__ __align__(16) char dyn[];
    float* Cs = (float*)dyn;
    int m0 = blockIdx.x * 128, n0 = blockIdx.y * 128;
    gemm128(A + (size_t)m0 * lda, lda, W + (size_t)n0 * ldw, ldw, K, dyn, Cs, 136);
    int tid = threadIdx.x;
    for (int e = tid; e < 4096; e += 256) {
        int r = e >> 5, c4 = (e & 31) * 4;
        float4 v = *(const float4*)(Cs + r * 136 + c4);
        if (bias) {
            float4 bv = *(const float4*)(bias + n0 + c4);
            v.x += bv.x; v.y += bv.y; v.z += bv.z; v.w += bv.w;
        }
        if (addW) {
            const bf16* aw = addW + (size_t)(m0 + r) * ldadd + n0 + c4;
            v.x += __bfloat162float(aw[0]); v.y += __bfloat162float(aw[1]);
            v.z += __bfloat162float(aw[2]); v.w += __bfloat162float(aw[3]);
        }
        bf162* o = (bf162*)(out + (size_t)(m0 + r) * ldo + n0 + c4);
        o[0] = cvt2(v.x, v.y); o[1] = cvt2(v.z, v.w);
    }
}

// ---------------- 128-tile vocab GEMM + fused LSE chunk (bias in LSE pass) ----------------
__global__ __launch_bounds__(256) void k_vocab128(const float* __restrict__ bias) {
    extern __shared__ __align__(16) char dyn[];
    __shared__ float sb[128];
    float* Cs = (float*)dyn;
    int tid = threadIdx.x;
    int m0 = blockIdx.x * 128, n0 = blockIdx.y * 128;
    if (tid < 128) sb[tid] = bias[n0 + tid];
    gemm128(g_avallb + (size_t)m0 * DDH, DDH, g_Wout + (size_t)n0 * DDH, DDH, DDH,
            dyn, Cs, 136);
    int row = tid >> 1, half = tid & 1;
    int rg = m0 + row;
    const float* Cr = Cs + row * 136 + half * 64;
    const float* bb = sb + half * 64;
    float m = -1e30f;
#pragma unroll 8
    for (int c = 0; c < 64; c++) m = fmaxf(m, Cr[c] + bb[c]);
    float mo = __shfl_xor_sync(0xffffffffu, m, 1);
    float mn = fmaxf(m, mo);
    float s = 0.f;
#pragma unroll 8
    for (int c = 0; c < 64; c++) s += __expf(Cr[c] + bb[c] - mn);
    s += __shfl_xor_sync(0xffffffffu, s, 1);
    if (rg < MR) {
        if (half == 0) {
            size_t co = ((size_t)rg * NTV + blockIdx.y) * 2;
            g_chunk[co + 0] = mn;
            g_chunk[co + 1] = s;
        }
        int loc = g_goldtok[rg] - n0 - half * 64;
        if (loc >= 0 && loc < 64) g_gold[rg] = Cr[loc] + bb[loc];
    }
}

// ---------------- persistent encoder: 64 steps ----------------
__global__ __launch_bounds__(256, 2) void k_enc_persist(
    const bf16* __restrict__ Wf, const bf16* __restrict__ Wr)
{
    extern __shared__ __align__(16) char dyn[];
    float* Cs = (float*)dyn;
    unsigned gen = 0;
    int p = blockIdx.x, tid = threadIdx.x;
    int d = p >> 4;
    int n0 = (p & 15) * 128;
    const bf16* A = g_hsb + d * (BB * HH);
    const bf16* W = (d ? Wr : Wf) + (size_t)n0 * HH;
    const float* pre_base = d ? g_Gr : g_Gf;
    for (int t = 0; t < TSR; t++) {
        gemm_core(A, HH, W, HH, HH, dyn, Cs, 136);
        for (int it = tid; it < 2048; it += 256) {
            int b = it >> 5, jl = it & 31;
            const float* cr = Cs + b * 136 + 4 * jl;
            const float* pre = pre_base + (size_t)(b * TSR + t) * 2048 + n0 + 4 * jl;
            float gi = cr[0] + pre[0];
            float gf = cr[1] + pre[1];
            float gg = cr[2] + pre[2];
            float go = cr[3] + pre[3];
            int j = (n0 >> 2) + jl;
            int si = d * (BB * HH) + (b << 9) + j;
            float c = sigf(gf) * g_cs[si] + sigf(gi) * tanhf(gg);
            float h = sigf(go) * tanhf(c);
            g_cs[si] = c;
            g_hsb[si] = __float2bfloat16(h);
            size_t o = (size_t)(b * TSR + t) * 1024 + d * 512 + j;
            g_Henc[o] = h; g_Cenc[o] = c; g_Hencb[o] = __float2bfloat16(h);
        }
        gsync(NBE, gen);
    }
}

// ---------------- persistent decoder: 63 steps, 2 phases/step ----------------
__global__ __launch_bounds__(256, 2) void k_dec_persist(const int* __restrict__ src_lens) {
    extern __shared__ __align__(16) char dyn[];
    float* Cs = (float*)dyn;
    unsigned gen = 0;
    int p = blockIdx.x, tid = threadIdx.x;
    for (int t = 0; t < TD; t++) {
        // ---- Phase A ----
        if (p < 128) {
            int nt = p & 31, ks = p >> 5;
            const bf16* A = g_hb + ks * 256;
            const bf16* W; int ldw;
            if (t == 0) { W = g_WdecR + (size_t)(nt * 128) * 2048 + 1024 + ks * 256; ldw = 2048; }
            else        { W = g_Wgate + (size_t)(nt * 128) * 1024 + ks * 256; ldw = 1024; }
            gemm_core(A, 1024, W, ldw, 256, dyn,
                      g_Pg + (size_t)ks * (64 * 4096) + nt * 128, 4096);
        } else if (t > 0) {
            int q = p - 128, b = q >> 1;
            float* sps = Cs;                         // 64 floats
            if (tid < 64) sps[tid] = g_spg[b * 64 + tid];
            __syncthreads();
            int c0 = (q & 1) * 2048 + tid * 8;
            float acc[8];
#pragma unroll
            for (int i = 0; i < 8; i++) acc[i] = 0.f;
            const bf16* Hc0 = g_HencC + (size_t)(b * 64) * 4096 + c0;
            for (int u = 0; u < 64; u++) {
                float pw = sps[u];
                float4 r0 = *(const float4*)(Hc0 + (size_t)u * 4096);
                const bf162* pp = (const bf162*)&r0;
#pragma unroll
                for (int i = 0; i < 4; i++) {
                    float2 f = __bfloat1622float2(pp[i]);
                    acc[2 * i] += pw * f.x; acc[2 * i + 1] += pw * f.y;
                }
            }
            float* cgw = g_ctxg + (size_t)b * 4096 + c0;
            *(float4*)cgw       = make_float4(acc[0], acc[1], acc[2], acc[3]);
            *(float4*)(cgw + 4) = make_float4(acc[4], acc[5], acc[6], acc[7]);
            __syncthreads();
        }
        gsyncH(NBD, gen);
        // ---- Phase B ----
        if (p < 64) {
            int b = p;
            float* sh = Cs;            // 1024
            float* sc = Cs + 1024;     // 64
            float* sp = Cs + 1088;     // 64
            const float* pre = g_Gdec + (size_t)((t << 6) + b) * 4096;
            const float* P0 = g_Pg + (size_t)b * 4096;
            const float* cg = g_ctxg + (size_t)b * 4096;
#pragma unroll
            for (int u = 0; u < 4; u++) {
                int j = tid + u * 256;
                int col = 4 * j;
                float4 gp = *(const float4*)(pre + col);
                float4 q0 = *(const float4*)(P0 + col);
                float4 q1 = *(const float4*)(P0 + 64 * 4096 + col);
                float4 q2 = *(const float4*)(P0 + 2 * 64 * 4096 + col);
                float4 q3 = *(const float4*)(P0 + 3 * 64 * 4096 + col);
                float gi = gp.x + q0.x + q1.x + q2.x + q3.x;
                float gf = gp.y + q0.y + q1.y + q2.y + q3.y;
                float gg = gp.z + q0.z + q1.z + q2.z + q3.z;
                float go = gp.w + q0.w + q1.w + q2.w + q3.w;
                if (t > 0) {
                    float4 ca = *(const float4*)(g_constA + col);
                    float4 cx = *(const float4*)(cg + col);
                    gi += ca.x + cx.x; gf += ca.y + cx.y;
                    gg += ca.z + cx.z; go += ca.w + cx.w;
                }
                int ci = (b << 10) + j;
                float c = sigf(gf) * g_c[ci] + sigf(gi) * tanhf(gg);
                float h = sigf(go) * tanhf(c);
                g_c[ci] = c;
                sh[j] = h;
                bf16 hb = __float2bfloat16(h);
                g_hb[ci] = hb;
                g_yall[(size_t)((t << 6) + b) * 2048 + j] = hb;
            }
            __syncthreads();
            // attention scores
            {
                int tt = tid >> 2, q = tid & 3;
                const bf162* He = (const bf162*)(g_Hencb + (size_t)(b * TSR + tt) * 1024 + q * 256);
                const float* hh = sh + q * 256;
                float s = 0.f;
#pragma unroll 8
                for (int j = 0; j < 128; j++) {
                    bf162 v = He[j];
                    s += hh[2 * j] * __bfloat162float(v.x) + hh[2 * j + 1] * __bfloat162float(v.y);
                }
                s += __shfl_xor_sync(0xffffffffu, s, 1);
                s += __shfl_xor_sync(0xffffffffu, s, 2);
                if (q == 0) sc[tt] = s;
            }
            __syncthreads();
            int L = src_lens[b];
            float m = -1e30f;
            for (int u = 0; u < 64; u++) if (u < L) m = fmaxf(m, sc[u]);
            float den = 0.f;
            for (int u = 0; u < 64; u++) if (u < L) den += __expf(sc[u] - m);
            if (tid < 64) {
                float pv = (tid < L) ? (__expf(sc[tid] - m) / den) : 0.f;
                sp[tid] = pv;
                g_spg[b * 64 + tid] = pv;
            }
            __syncthreads();
            // ctx (1024) -> yall[..., 1024:2048]
            {
                int j0 = tid * 4;
                float a0 = 0.f, a1 = 0.f, a2 = 0.f, a3 = 0.f;
                for (int u = 0; u < L; u++) {
                    float pw = sp[u];
                    const bf162* Hr = (const bf162*)(g_Hencb + (size_t)(b * TSR + u) * 1024 + j0);
                    bf162 v0 = Hr[0], v1 = Hr[1];
                    a0 += pw * __bfloat162float(v0.x); a1 += pw * __bfloat162float(v0.y);
                    a2 += pw * __bfloat162float(v1.x); a3 += pw * __bfloat162float(v1.y);
                }
                bf162* co = (bf162*)(g_yall + (size_t)((t << 6) + b) * 2048 + 1024 + j0);
                co[0] = cvt2(a0, a1); co[1] = cvt2(a2, a3);
            }
        }
        gsyncH(NBD, gen);
    }
}

// ---------------- decoder init (fp32 path, one-time) ----------------
__global__ void k_final(const int* __restrict__ src_lens) {
    int i = blockIdx.x * blockDim.x + threadIdx.x;    // < 64*2048
    int b = i >> 11, j = i & 2047;
    int last = src_lens[b] - 1;
    size_t o = (size_t)(b * TSR + last) * 1024;
    g_final[i] = (j < 1024) ? g_Henc[o + j] : g_Cenc[o + j - 1024];
}

__global__ void k_sgemm_init(const float* __restrict__ W) {
    __shared__ float As[16][64];
    __shared__ float Ws[16][32];
    int z = blockIdx.z;
    int koff = z * 512;
    int tid = threadIdx.x;
    int n0 = blockIdx.x * 32;
    int ty = tid >> 3, tx = tid & 7;
    int lr = tid >> 1, lc = (tid & 1) * 8;
    int wr = tid >> 2, wc = (tid & 3) * 4;
    float acc[4][4];
#pragma unroll
    for (int i = 0; i < 4; i++)
#pragma unroll
        for (int j = 0; j < 4; j++) acc[i][j] = 0.f;
    const float* Ab = g_final + (size_t)lr * 2048 + koff + lc;
    const float* Wb = W + (size_t)(n0 + wr) * 2048 + koff + wc;
    for (int k0 = 0; k0 < 512; k0 += 16) {
        float4 a0 = *(const float4*)(Ab + k0);
        float4 a1 = *(const float4*)(Ab + k0 + 4);
        float4 b0 = *(const float4*)(Wb + k0);
        __syncthreads();
        As[lc + 0][lr] = a0.x; As[lc + 1][lr] = a0.y; As[lc + 2][lr] = a0.z; As[lc + 3][lr] = a0.w;
        As[lc + 4][lr] = a1.x; As[lc + 5][lr] = a1.y; As[lc + 6][lr] = a1.z; As[lc + 7][lr] = a1.w;
        Ws[wc + 0][wr] = b0.x; Ws[wc + 1][wr] = b0.y; Ws[wc + 2][wr] = b0.z; Ws[wc + 3][wr] = b0.w;
        __syncthreads();
#pragma unroll
        for (int kk = 0; kk < 16; kk++) {
            float a[4], b[4];
#pragma unroll
            for (int i = 0; i < 4; i++) a[i] = As[kk][ty * 4 + i];
#pragma unroll
            for (int j = 0; j < 4; j++) b[j] = Ws[kk][tx * 4 + j];
#pragma unroll
            for (int i = 0; i < 4; i++)
#pragma unroll
                for (int j = 0; j < 4; j++) acc[i][j] += a[i] * b[j];
        }
    }
    float* Pz = g_Phid + (size_t)z * (BB * DDH);
#pragma unroll
    for (int i = 0; i < 4; i++)
#pragma unroll
        for (int j = 0; j < 4; j++)
            Pz[(ty * 4 + i) * DDH + n0 + tx * 4 + j] = acc[i][j];
}

__global__ void k_init(const float* __restrict__ init_b) {
    int i = blockIdx.x * blockDim.x + threadIdx.x;    // < 64*1024
    int j = i & 1023;
    float c = init_b[j];
#pragma unroll
    for (int s = 0; s < 4; s++) c += g_Phid[s * (BB * DDH) + i];
    g_c[i] = c;
    g_hb[i] = __float2bfloat16(tanhf(c));
}

// ---------------- per-row LSE combine + masked sum ----------------
__global__ void k_rowlse() {
    int tid = threadIdx.x;                 // 256
    int b = tid >> 2, q = tid & 3;
    int row = blockIdx.x * 64 + b;
    const float* ch = g_chunk + (size_t)row * NTV * 2;
    float m = -1e30f;
    for (int i = q; i < NTV; i += 4) m = fmaxf(m, ch[2 * i]);
    m = fmaxf(m, __shfl_xor_sync(0xffffffffu, m, 1));
    m = fmaxf(m, __shfl_xor_sync(0xffffffffu, m, 2));
    float s = 0.f;
    for (int i = q; i < NTV; i += 4) s += ch[2 * i + 1] * __expf(ch[2 * i] - m);
    s += __shfl_xor_sync(0xffffffffu, s, 1);
    s += __shfl_xor_sync(0xffffffffu, s, 2);
    if (q == 0) {
        float lse = m + logf(s);
        g_rowval[row] = (g_gold[row] - lse) * g_maskf[row];
    }
}

__global__ void k_sum(float* __restrict__ out) {
    __shared__ float sm[256];
    int tid = threadIdx.x;
    float s = 0.f;
    for (int i = tid; i < MR; i += 256) s += g_rowval[i];
    sm[tid] = s;
    __syncthreads();
    for (int st = 128; st > 0; st >>= 1) {
        if (tid < st) sm[tid] += sm[tid + st];
        __syncthreads();
    }
    if (tid == 0) out[0] = sm[0];
}

// ---------------- launch ----------------
extern "C" void kernel_launch(void* const* d_in, const int* in_sizes, int n_in,
                              void* d_out, int out_size) {
    (void)in_sizes; (void)n_in; (void)out_size;
    const int*   src_tokens = (const int*)d_in[0];
    const int*   src_lens   = (const int*)d_in[1];
    const int*   trg_tokens = (const int*)d_in[2];
    const int*   trg_lens   = (const int*)d_in[3];
    const float* src_emb    = (const float*)d_in[4];
    const float* trg_emb    = (const float*)d_in[5];
    const float* enc_Wih    = (const float*)d_in[6];
    const float* enc_Whh    = (const float*)d_in[7];
    const float* enc_b      = (const float*)d_in[8];
    const float* rev_Wih    = (const float*)d_in[9];
    const float* rev_Whh    = (const float*)d_in[10];
    const float* rev_b      = (const float*)d_in[11];
    const float* dec_Wih    = (const float*)d_in[12];
    const float* dec_Whh    = (const float*)d_in[13];
    const float* dec_b      = (const float*)d_in[14];
    const float* hid_W      = (const float*)d_in[15];
    const float* hid_b      = (const float*)d_in[16];
    const float* out_W      = (const float*)d_in[17];
    const float* out_b      = (const float*)d_in[18];
    const float* init_W     = (const float*)d_in[19];
    const float* init_b     = (const float*)d_in[20];

    bf16 *p_svb, *p_tvb, *p_Wencf, *p_Wencr, *p_Whhf, *p_Whhr, *p_WdecE, *p_WhidB,
         *p_Wout, *p_WhidLT, *p_WhidRT, *p_Wgate, *p_WcombC, *p_HencC, *p_Hencb,
         *p_WdecR, *p_yall, *p_avallb;
    float *p_Gf, *p_Gr, *p_Gdec, *p_bencf, *p_bencr, *p_bdec;
    cudaGetSymbolAddress((void**)&p_svb, g_svb);
    cudaGetSymbolAddress((void**)&p_tvb, g_tvb);
    cudaGetSymbolAddress((void**)&p_Wencf, g_WencfP);
    cudaGetSymbolAddress((void**)&p_Wencr, g_WencrP);
    cudaGetSymbolAddress((void**)&p_Whhf, g_WhhfP);
    cudaGetSymbolAddress((void**)&p_Whhr, g_WhhrP);
    cudaGetSymbolAddress((void**)&p_WdecE, g_WdecE);
    cudaGetSymbolAddress((void**)&p_WhidB, g_WhidB);
    cudaGetSymbolAddress((void**)&p_Wout, g_Wout);
    cudaGetSymbolAddress((void**)&p_WhidLT, g_WhidLT);
    cudaGetSymbolAddress((void**)&p_WhidRT, g_WhidRT);
    cudaGetSymbolAddress((void**)&p_Wgate, g_Wgate);
    cudaGetSymbolAddress((void**)&p_WcombC, g_WcombC);
    cudaGetSymbolAddress((void**)&p_HencC, g_HencC);
    cudaGetSymbolAddress((void**)&p_Hencb, g_Hencb);
    cudaGetSymbolAddress((void**)&p_WdecR, g_WdecR);
    cudaGetSymbolAddress((void**)&p_yall, g_yall);
    cudaGetSymbolAddress((void**)&p_avallb, g_avallb);
    cudaGetSymbolAddress((void**)&p_Gf, g_Gf);
    cudaGetSymbolAddress((void**)&p_Gr, g_Gr);
    cudaGetSymbolAddress((void**)&p_Gdec, g_Gdec);
    cudaGetSymbolAddress((void**)&p_bencf, g_bencfP);
    cudaGetSymbolAddress((void**)&p_bencr, g_bencrP);
    cudaGetSymbolAddress((void**)&p_bdec, g_bdecP);

    // dynamic smem opt-in
    cudaFuncSetAttribute(k_ff128, cudaFuncAttributeMaxDynamicSharedMemorySize, DYN2);
    cudaFuncSetAttribute(k_gemm128_b, cudaFuncAttributeMaxDynamicSharedMemorySize, DYN2);
    cudaFuncSetAttribute(k_vocab128, cudaFuncAttributeMaxDynamicSharedMemorySize, DYN2);
    cudaFuncSetAttribute(k_enc_persist, cudaFuncAttributeMaxDynamicSharedMemorySize, DYN_SMEM);
    cudaFuncSetAttribute(k_dec_persist, cudaFuncAttributeMaxDynamicSharedMemorySize, DYN_SMEM);

    k_zero_state<<<256, 256>>>();
    k_zeropad<<<512, 256>>>();
    k_gather_src<<<BB * TSR, 128>>>(src_tokens, src_emb);
    k_gather_trg<<<MR, 128>>>(trg_tokens, trg_lens, trg_emb);

    // weight conversions + gate-interleave permutations
    k_permW512<<<2048, 128>>>(enc_Wih, p_Wencf, 512, 512);
    k_permW512<<<2048, 128>>>(rev_Wih, p_Wencr, 512, 512);
    k_permW512<<<2048, 128>>>(enc_Whh, p_Whhf, 512, 512);
    k_permW512<<<2048, 128>>>(rev_Whh, p_Whhr, 512, 512);
    k_permW512<<<4096, 128>>>(dec_Wih, p_WdecE, 1024, 1536);
    k_permDecR<<<4096, 256>>>(dec_Wih, dec_Whh);
    k_permB<<<8, 256>>>(enc_b, p_bencf, 512);
    k_permB<<<8, 256>>>(rev_b, p_bencr, 512);
    k_permB<<<16, 256>>>(dec_b, p_bdec, 1024);
    k_f2b<<<(DDH * 2048 / 4 + 255) / 256, 256>>>(hid_W, p_WhidB, DDH * 2048 / 4);
    k_f2b<<<(VOC * DDH / 4 + 255) / 256, 256>>>(out_W, p_Wout, VOC * DDH / 4);
    k_transpose_hid<<<dim3(32, 32, 2), dim3(32, 8)>>>(hid_W);
    k_const<<<512, 256>>>(hid_b);

    // composed decoder weights: Wgate = WA@WhidL + Whh ; WcombC = WA@WhidR
    k_gemm128_b<<<dim3(32, 8), 256, DYN2>>>(p_WdecR, 2048, p_WhidLT, 1024, 1024,
                                            (const float*)0, p_WdecR + 1024, 2048,
                                            p_Wgate, 1024);
    k_gemm128_b<<<dim3(32, 8), 256, DYN2>>>(p_WdecR, 2048, p_WhidRT, 1024, 1024,
                                            (const float*)0, (const bf16*)0, 0,
                                            p_WcombC, 1024);

    // input projections (tensor cores, interleaved outputs)
    k_ff128<<<dim3(32, 16), 256, DYN2>>>(p_svb, EE, p_Wencf, EE, p_bencf, p_Gf, 2048, EE);
    k_ff128<<<dim3(32, 16), 256, DYN2>>>(p_svb, EE, p_Wencr, EE, p_bencr, p_Gr, 2048, EE);
    k_ff128<<<dim3(32, 32), 256, DYN2>>>(p_tvb, EE, p_WdecE, EE, p_bdec, p_Gdec, 4096, EE);

    // encoder recurrence (persistent)
    k_enc_persist<<<NBE, 256, DYN_SMEM>>>(p_Whhf, p_Whhr);

    // HencC = Henc @ WcombC^T  (needs encoder output)
    k_gemm128_b<<<dim3(32, 32), 256, DYN2>>>(p_Hencb, 1024, p_WcombC, 1024, 1024,
                                             (const float*)0, (const bf16*)0, 0,
                                             p_HencC, 4096);

    // decoder init state
    k_final<<<512, 256>>>(src_lens);
    k_sgemm_init<<<dim3(32, 1, 4), 128>>>(init_W);
    k_init<<<256, 256>>>(init_b);

    // decoder recurrence (persistent, 2 phases/step)
    k_dec_persist<<<NBD, 256, DYN_SMEM>>>(src_lens);

    // deferred hid GEMM: avall = [h|ctx] @ hid_W^T + hid_b
    k_gemm128_b<<<dim3(32, 8), 256, DYN2>>>(p_yall, 2048, p_WhidB, 2048, 2048,
                                            hid_b, (const bf16*)0, 0, p_avallb, 1024);

    // vocab projection + LSE (128-tile)
    k_vocab128<<<dim3(32, NTV), 256, DYN2>>>(out_b);
    k_rowlse<<<63, 256>>>();
    k_sum<<<1, 256>>>((float*)d_out);
}

// round 13
// speedup vs baseline: 1.0117x; 1.0117x over previous
#include <cuda_runtime.h>
#include <cuda_bf16.h>
#include <mma.h>
#include <math.h>
#include <stdint.h>
using namespace nvcuda;

// ---------------- problem constants ----------------
#define BB   64      // batch
#define TSR  64      // src len
#define TTR  64      // trg len
#define EE   512     // embedding
#define HH   512     // encoder hidden per dir
#define DDH  1024    // decoder hidden
#define VOC  32000
#define TD   63              // decode steps
#define MR   (TD*BB)         // 4032 rows
#define MRP  4096            // padded row count for 128-tiles
#define NTV  (VOC/128)       // 250 column chunks (128 cols each) for LSE
#define NBE  32              // encoder persistent grid
#define NBD  256             // decoder persistent grid

#define AS_STAGE (64*72)
#define WS_STAGE (128*72)
#define DYN_SMEM ((2*AS_STAGE + 2*WS_STAGE) * 2)   // 55296 bytes (64x128 core)

#define G128_STAGE (128*72)                         // bf16 elems per tensor per stage
#define DYN2 (4*G128_STAGE*2)                       // 73728 bytes (128x128 core)

#define V_ASTAGE (128*72)
#define V_WSTAGE (256*72)
#define DYN3 ((2*V_ASTAGE + 2*V_WSTAGE) * 2)        // 110592 bytes (128x256 vocab core)

typedef __nv_bfloat16 bf16;
typedef __nv_bfloat162 bf162;

// ---------------- static device scratch ----------------
__device__ bf16 g_svb  [BB*TSR*EE];       // src embedded bf16, row = b*TSR+t
__device__ bf16 g_tvb  [MRP*EE];          // trg embedded bf16, row = t*BB+b (padded)
__device__ bf16 g_WencfP[4*HH*EE];        // enc_Wih bf16, gate-interleaved rows
__device__ bf16 g_WencrP[4*HH*EE];
__device__ bf16 g_WhhfP [4*HH*HH];        // enc_Whh bf16 interleaved
__device__ bf16 g_WhhrP [4*HH*HH];
__device__ bf16 g_WdecE [4*DDH*EE];       // dec_Wih[:, :512] interleaved
__device__ bf16 g_WdecR [4*DDH*2048];     // [dec_Wih[:,512:1536] | dec_Whh] interleaved
__device__ bf16 g_WhidB [DDH*2*DDH];      // hid_W bf16 plain [1024][2048]
__device__ bf16 g_WhidLT[DDH*DDH];        // hid_W left half transposed  [k][j]
__device__ bf16 g_WhidRT[DDH*DDH];        // hid_W right half transposed [k][j]
__device__ bf16 g_Wgate [4*DDH*DDH];      // WA@WhidL + Whh (interleaved rows)
__device__ bf16 g_WcombC[4*DDH*DDH];      // WA@WhidR (interleaved rows)
__device__ bf16 g_HencC [BB*TSR*4*DDH];   // Henc @ WcombC^T  [(b*64+u)][4096]
__device__ bf16 g_Wout  [VOC*DDH];        // out_W bf16 plain
__device__ bf16 g_avallb[MRP*DDH];        // all av rows bf16 (padded)
__device__ bf16 g_yall  [MRP*2048];       // [h|ctx] rows (padded)

__device__ float g_bencfP[4*HH];          // permuted biases (fp32)
__device__ float g_bencrP[4*HH];
__device__ float g_bdecP [4*DDH];
__device__ float g_constA[4*DDH];         // WA_P @ hid_b

__device__ float g_Gf   [BB*TSR*4*HH];    // enc fwd preact (interleaved cols)
__device__ float g_Gr   [BB*TSR*4*HH];
__device__ float g_Gdec [MRP*4*DDH];      // dec preact (emb part + bias, interleaved)
__device__ float g_Henc [BB*TSR*2*HH];    // fp32 (for final-state gather)
__device__ float g_Cenc [BB*TSR*2*HH];
__device__ bf16  g_Hencb[BB*TSR*2*HH];    // bf16 copy for attention / HencC GEMM
__device__ bf16  g_hsb  [2*BB*HH];        // enc running h bf16 (both dirs)
__device__ float g_cs   [2*BB*HH];        // enc running c fp32
__device__ float g_c    [BB*DDH];         // dec c fp32
__device__ bf16  g_hb   [BB*DDH];         // dec h bf16 (gates GEMM input)
__device__ float g_ctxg [BB*4*DDH];       // ctx-contribution to next gates (fp32)
__device__ float g_spg  [BB*64];          // softmax probs (global, for ctxg blocks)
__device__ float g_Pg   [4*BB*4*DDH];     // gates split-K partials (4 x [64,4096])
__device__ float g_Phid [4*BB*DDH];       // init-GEMM split-K partials
__device__ float g_final[BB*2*DDH];       // concat(Henc,Cenc) at last
__device__ float g_chunk[MR*NTV*2];       // per-128col-chunk (max, sumexp)
__device__ float g_gold [MR];
__device__ int   g_goldtok[MR];
__device__ float g_maskf[MR];
__device__ float g_rowval[MR];
__device__ unsigned g_bar[8];             // [0]=cntE [1]=genE [4]=cntD [5]=genD

__device__ __forceinline__ float sigf(float x) { return 1.0f / (1.0f + expf(-x)); }
__device__ __forceinline__ bf162 cvt2(float a, float b) {
    return __float22bfloat162_rn(make_float2(a, b));
}

// ---------------- device-wide software barrier ----------------
__device__ __forceinline__ void gsync(int base, unsigned nb, unsigned& mygen) {
    __threadfence();
    __syncthreads();
    if (threadIdx.x == 0) {
        unsigned g = mygen;
        if (atomicAdd(&g_bar[base], 1u) == nb - 1u) {
            atomicExch(&g_bar[base], 0u);
            __threadfence();
            atomicExch(&g_bar[base + 1], g + 1u);
        } else {
            volatile unsigned* vg = (volatile unsigned*)&g_bar[base + 1];
            while (*vg == g) __nanosleep(64);
        }
    }
    mygen++;
    __syncthreads();
}

// ============ 64x128 GEMM core (persistent kernels), K-tile 64 ============
__device__ __forceinline__ void gemm_core(
    const bf16* __restrict__ A, int lda,
    const bf16* __restrict__ W, int ldw,
    int K, char* smem, float* out, int ldo)
{
    bf16* As = (bf16*)smem;                  // 2 stages x 64 x 72
    bf16* Ws = (bf16*)smem + 2 * AS_STAGE;   // 2 stages x 128 x 72
    int tid = threadIdx.x;
    int wid = tid >> 5;
    int wr = (wid & 1) * 32, wc = (wid >> 1) * 32;

    wmma::fragment<wmma::accumulator, 16, 16, 16, float> acc[2][2];
#pragma unroll
    for (int i = 0; i < 2; i++)
#pragma unroll
        for (int j = 0; j < 2; j++) wmma::fill_fragment(acc[i][j], 0.f);

    int ar = tid >> 2, ac = (tid & 3) * 16;
    int wq = tid >> 1, wz = (tid & 1) * 32;
    const bf16* Ap = A + (size_t)ar * lda + ac;
    const bf16* Wp = W + (size_t)wq * ldw + wz;

    float4 a0 = *(const float4*)Ap;
    float4 a1 = *(const float4*)(Ap + 8);
    float4 w0 = *(const float4*)Wp;
    float4 w1 = *(const float4*)(Wp + 8);
    float4 w2 = *(const float4*)(Wp + 16);
    float4 w3 = *(const float4*)(Wp + 24);
    *(float4*)&As[ar * 72 + ac]     = a0;
    *(float4*)&As[ar * 72 + ac + 8] = a1;
    *(float4*)&Ws[wq * 72 + wz]      = w0;
    *(float4*)&Ws[wq * 72 + wz + 8]  = w1;
    *(float4*)&Ws[wq * 72 + wz + 16] = w2;
    *(float4*)&Ws[wq * 72 + wz + 24] = w3;

    int niter = K >> 6;
    int cur = 0;
    for (int it = 0; it < niter; ++it) {
        __syncthreads();
        if (it + 1 < niter) {
            const bf16* Apn = Ap + (it + 1) * 64;
            const bf16* Wpn = Wp + (it + 1) * 64;
            a0 = *(const float4*)Apn;
            a1 = *(const float4*)(Apn + 8);
            w0 = *(const float4*)Wpn;
            w1 = *(const float4*)(Wpn + 8);
            w2 = *(const float4*)(Wpn + 16);
            w3 = *(const float4*)(Wpn + 24);
        }
        const bf16* Ab = As + cur * AS_STAGE;
        const bf16* Wb = Ws + cur * WS_STAGE;
#pragma unroll
        for (int kk = 0; kk < 64; kk += 16) {
            wmma::fragment<wmma::matrix_a, 16, 16, 16, bf16, wmma::row_major> af[2];
            wmma::fragment<wmma::matrix_b, 16, 16, 16, bf16, wmma::col_major> bfr[2];
            wmma::load_matrix_sync(af[0], Ab + wr * 72 + kk, 72);
            wmma::load_matrix_sync(af[1], Ab + (wr + 16) * 72 + kk, 72);
            wmma::load_matrix_sync(bfr[0], Wb + wc * 72 + kk, 72);
            wmma::load_matrix_sync(bfr[1], Wb + (wc + 16) * 72 + kk, 72);
#pragma unroll
            for (int i = 0; i < 2; i++)
#pragma unroll
                for (int j = 0; j < 2; j++)
                    wmma::mma_sync(acc[i][j], af[i], bfr[j], acc[i][j]);
        }
        if (it + 1 < niter) {
            int nb = cur ^ 1;
            *(float4*)&As[nb * AS_STAGE + ar * 72 + ac]     = a0;
            *(float4*)&As[nb * AS_STAGE + ar * 72 + ac + 8] = a1;
            *(float4*)&Ws[nb * WS_STAGE + wq * 72 + wz]      = w0;
            *(float4*)&Ws[nb * WS_STAGE + wq * 72 + wz + 8]  = w1;
            *(float4*)&Ws[nb * WS_STAGE + wq * 72 + wz + 16] = w2;
            *(float4*)&Ws[nb * WS_STAGE + wq * 72 + wz + 24] = w3;
        }
        cur ^= 1;
    }
    __syncthreads();
#pragma unroll
    for (int i = 0; i < 2; i++)
#pragma unroll
        for (int j = 0; j < 2; j++)
            wmma::store_matrix_sync(out + (size_t)(wr + i * 16) * ldo + wc + j * 16,
                                    acc[i][j], ldo, wmma::mem_row_major);
    __syncthreads();
}

// ============ 128x128 GEMM core (feed-forward), warp tile 32x64 ============
__device__ __forceinline__ void gemm128(
    const bf16* __restrict__ A, int lda,
    const bf16* __restrict__ W, int ldw,
    int K, char* smem, float* out, int ldo)
{
    bf16* As = (bf16*)smem;                     // 2 stages x 128 x 72
    bf16* Ws = (bf16*)smem + 2 * G128_STAGE;    // 2 stages x 128 x 72
    int tid = threadIdx.x;
    int wid = tid >> 5;
    int wm = (wid & 3) * 32, wn = (wid >> 2) * 64;

    wmma::fragment<wmma::accumulator, 16, 16, 16, float> acc[2][4];
#pragma unroll
    for (int i = 0; i < 2; i++)
#pragma unroll
        for (int j = 0; j < 4; j++) wmma::fill_fragment(acc[i][j], 0.f);

    int r = tid >> 1, hc = (tid & 1) * 32;
    const bf16* Ap = A + (size_t)r * lda + hc;
    const bf16* Wp = W + (size_t)r * ldw + hc;

    float4 a0 = *(const float4*)Ap;
    float4 a1 = *(const float4*)(Ap + 8);
    float4 a2 = *(const float4*)(Ap + 16);
    float4 a3 = *(const float4*)(Ap + 24);
    float4 w0 = *(const float4*)Wp;
    float4 w1 = *(const float4*)(Wp + 8);
    float4 w2 = *(const float4*)(Wp + 16);
    float4 w3 = *(const float4*)(Wp + 24);
    {
        uint32_t o = (uint32_t)r * 72u + (uint32_t)hc;
        *(float4*)&As[o] = a0; *(float4*)&As[o + 8] = a1;
        *(float4*)&As[o + 16] = a2; *(float4*)&As[o + 24] = a3;
        *(float4*)&Ws[o] = w0; *(float4*)&Ws[o + 8] = w1;
        *(float4*)&Ws[o + 16] = w2; *(float4*)&Ws[o + 24] = w3;
    }

    int niter = K >> 6;
    int cur = 0;
    for (int it = 0; it < niter; ++it) {
        __syncthreads();
        if (it + 1 < niter) {
            const bf16* Apn = Ap + (it + 1) * 64;
            const bf16* Wpn = Wp + (it + 1) * 64;
            a0 = *(const float4*)Apn;       a1 = *(const float4*)(Apn + 8);
            a2 = *(const float4*)(Apn + 16); a3 = *(const float4*)(Apn + 24);
            w0 = *(const float4*)Wpn;       w1 = *(const float4*)(Wpn + 8);
            w2 = *(const float4*)(Wpn + 16); w3 = *(const float4*)(Wpn + 24);
        }
        const bf16* Ab = As + cur * G128_STAGE;
        const bf16* Wb = Ws + cur * G128_STAGE;
#pragma unroll
        for (int kk = 0; kk < 64; kk += 16) {
            wmma::fragment<wmma::matrix_a, 16, 16, 16, bf16, wmma::row_major> af[2];
            wmma::fragment<wmma::matrix_b, 16, 16, 16, bf16, wmma::col_major> bfr[4];
            wmma::load_matrix_sync(af[0], Ab + wm * 72 + kk, 72);
            wmma::load_matrix_sync(af[1], Ab + (wm + 16) * 72 + kk, 72);
#pragma unroll
            for (int j = 0; j < 4; j++)
                wmma::load_matrix_sync(bfr[j], Wb + (wn + j * 16) * 72 + kk, 72);
#pragma unroll
            for (int i = 0; i < 2; i++)
#pragma unroll
                for (int j = 0; j < 4; j++)
                    wmma::mma_sync(acc[i][j], af[i], bfr[j], acc[i][j]);
        }
        if (it + 1 < niter) {
            int nb = cur ^ 1;
            uint32_t o = (uint32_t)nb * G128_STAGE + (uint32_t)r * 72u + (uint32_t)hc;
            *(float4*)&As[o] = a0; *(float4*)&As[o + 8] = a1;
            *(float4*)&As[o + 16] = a2; *(float4*)&As[o + 24] = a3;
            *(float4*)&Ws[o] = w0; *(float4*)&Ws[o + 8] = w1;
            *(float4*)&Ws[o + 16] = w2; *(float4*)&Ws[o + 24] = w3;
        }
        cur ^= 1;
    }
    __syncthreads();
#pragma unroll
    for (int i = 0; i < 2; i++)
#pragma unroll
        for (int j = 0; j < 4; j++)
            wmma::store_matrix_sync(out + (size_t)(wm + i * 16) * ldo + wn + j * 16,
                                    acc[i][j], ldo, wmma::mem_row_major);
    __syncthreads();
}

// ---------------- conversions / permutations ----------------
__global__ void k_f2b(const float* __restrict__ x, bf16* __restrict__ y, int n4) {
    int i = blockIdx.x * blockDim.x + threadIdx.x;
    if (i < n4) {
        float4 v = ((const float4*)x)[i];
        ((bf162*)y)[2 * i]     = cvt2(v.x, v.y);
        ((bf162*)y)[2 * i + 1] = cvt2(v.z, v.w);
    }
}

__global__ void k_permW512(const float* __restrict__ W, bf16* __restrict__ out,
                           int J, int ldin) {
    int row = blockIdx.x;
    int j = row >> 2, g = row & 3;
    const float4* src = (const float4*)(W + (size_t)(g * J + j) * ldin);
    bf162* dst = (bf162*)(out + (size_t)row * 512);
    int t = threadIdx.x;                   // 128
    float4 v = src[t];
    dst[2 * t]     = cvt2(v.x, v.y);
    dst[2 * t + 1] = cvt2(v.z, v.w);
}

__global__ void k_permDecR(const float* __restrict__ Wih, const float* __restrict__ Whh) {
    int row = blockIdx.x;                  // 4096
    int j = row >> 2, g = row & 3;
    int t = threadIdx.x;                   // 256, 8 elems each
    const float* src = (t < 128)
        ? (Wih + (size_t)(g * 1024 + j) * 1536 + 512 + t * 8)
        : (Whh + (size_t)(g * 1024 + j) * 1024 + (t - 128) * 8);
    bf162* dst = (bf162*)(g_WdecR + (size_t)row * 2048 + t * 8);
    float4 a = *(const float4*)src;
    float4 b = *(const float4*)(src + 4);
    dst[0] = cvt2(a.x, a.y); dst[1] = cvt2(a.z, a.w);
    dst[2] = cvt2(b.x, b.y); dst[3] = cvt2(b.z, b.w);
}

__global__ void k_permB(const float* __restrict__ b, float* __restrict__ out, int J) {
    int i = blockIdx.x * blockDim.x + threadIdx.x;
    if (i < 4 * J) { int j = i >> 2, g = i & 3; out[i] = b[g * J + j]; }
}

// transpose hid_W halves -> bf16 [k][j]
__global__ void k_transpose_hid(const float* __restrict__ W) {
    __shared__ float tile[32][33];
    int half = blockIdx.z;
    int k0 = blockIdx.x * 32;
    int j0 = blockIdx.y * 32;
    int tx = threadIdx.x, ty = threadIdx.y;   // 32 x 8
#pragma unroll
    for (int i = 0; i < 32; i += 8)
        tile[ty + i][tx] = W[(size_t)(j0 + ty + i) * 2048 + half * 1024 + k0 + tx];
    __syncthreads();
    bf16* out = half ? g_WhidRT : g_WhidLT;
#pragma unroll
    for (int i = 0; i < 32; i += 8)
        out[(size_t)(k0 + ty + i) * 1024 + j0 + tx] = __float2bfloat16(tile[tx][ty + i]);
}

// constA[row] = dot(WA_P[row,:], hid_b)
__global__ void k_const(const float* __restrict__ hid_b) {
    int row = blockIdx.x * 8 + (threadIdx.x >> 5);
    int lane = threadIdx.x & 31;
    const bf16* wr = g_WdecR + (size_t)row * 2048;
    float s = 0.f;
    for (int k = lane; k < 1024; k += 32) s += __bfloat162float(wr[k]) * hid_b[k];
#pragma unroll
    for (int o = 16; o > 0; o >>= 1) s += __shfl_xor_sync(0xffffffffu, s, o);
    if (lane == 0) g_constA[row] = s;
}

// ---------------- init / gathers ----------------
__global__ void k_zero_state() {
    int i = blockIdx.x * blockDim.x + threadIdx.x;
    if (i < 2 * BB * HH) { g_cs[i] = 0.f; g_hsb[i] = __float2bfloat16(0.f); }
    if (i < 8) g_bar[i] = 0u;
}

// zero the pad rows (rows MR..MRP) of avall / tvb / yall
__global__ void k_zeropad() {
    int i = blockIdx.x * blockDim.x + threadIdx.x;
    bf16 z = __float2bfloat16(0.f);
    if (i < 64 * 1024) g_avallb[MR * DDH + i] = z;
    if (i < 64 * 512)  g_tvb[MR * EE + i] = z;
    if (i < 64 * 2048) g_yall[(size_t)MR * 2048 + i] = z;
}

__global__ void k_gather_src(const int* __restrict__ tok, const float* __restrict__ emb) {
    int r = blockIdx.x;
    int v = tok[r];
    float4 val = ((const float4*)(emb + (size_t)v * EE))[threadIdx.x];
    bf162* d = (bf162*)(g_svb + (size_t)r * EE + threadIdx.x * 4);
    d[0] = cvt2(val.x, val.y); d[1] = cvt2(val.z, val.w);
}

__global__ void k_gather_trg(const int* __restrict__ tok, const int* __restrict__ lens,
                             const float* __restrict__ emb) {
    int r = blockIdx.x;                    // t*BB + b
    int t = r >> 6, b = r & 63;
    int v = tok[b * TTR + t];
    float4 val = ((const float4*)(emb + (size_t)v * EE))[threadIdx.x];
    bf162* d = (bf162*)(g_tvb + (size_t)r * EE + threadIdx.x * 4);
    d[0] = cvt2(val.x, val.y); d[1] = cvt2(val.z, val.w);
    if (threadIdx.x == 0) {
        g_goldtok[r] = tok[b * TTR + t + 1];
        g_maskf[r] = ((t + 1) < lens[b]) ? 1.0f : 0.0f;
    }
}

// ---------------- 128-tile feed-forward GEMM (fp32 out): C = A @ W^T + bias ----------------
__global__ __launch_bounds__(256) void k_ff128(
    const bf16* __restrict__ A, int lda,
    const bf16* __restrict__ W, int ldw,
    const float* __restrict__ bias,
    float* __restrict__ C, int ldc, int K)
{
    extern __shared__ __align__(16) char dyn[];
    float* Cs = (float*)dyn;
    int m0 = blockIdx.x * 128, n0 = blockIdx.y * 128;
    gemm128(A + (size_t)m0 * lda, lda, W + (size_t)n0 * ldw, ldw, K, dyn, Cs, 136);
    int tid = threadIdx.x;
    for (int e = tid; e < 4096; e += 256) {
        int r = e >> 5, c4 = (e & 31) * 4;
        float4 v = *(const float4*)(Cs + r * 136 + c4);
        float4 bv = *(const float4*)(bias + n0 + c4);
        v.x += bv.x; v.y += bv.y; v.z += bv.z; v.w += bv.w;
        *(float4*)(C + (size_t)(m0 + r) * ldc + n0 + c4) = v;
    }
}

// ---------------- 128-tile GEMM (bf16 out, optional bias / bf16 add) ----------------
__global__ __launch_bounds__(256) void k_gemm128_b(
    const bf16* __restrict__ A, int lda,
    const bf16* __restrict__ W, int ldw, int K,
    const float* __restrict__ bias,
    const bf16* __restrict__ addW, int ldadd,
    bf16* __restrict__ out, int ldo)
{
    extern __shared__ __align__(16) char dyn[];
    float* Cs = (float*)dyn;
    int m0 = blockIdx.x * 128, n0 = blockIdx.y * 128;
    gemm128(A + (size_t)m0 * lda, lda, W + (size_t)n0 * ldw, ldw, K, dyn, Cs, 136);
    int tid = threadIdx.x;
    for (int e = tid; e < 4096; e += 256) {
        int r = e >> 5, c4 = (e & 31) * 4;
        float4 v = *(const float4*)(Cs + r * 136 + c4);
        if (bias) {
            float4 bv = *(const float4*)(bias + n0 + c4);
            v.x += bv.x; v.y += bv.y; v.z += bv.z; v.w += bv.w;
        }
        if (addW) {
            const bf16* aw = addW + (size_t)(m0 + r) * ldadd + n0 + c4;
            v.x += __bfloat162float(aw[0]); v.y += __bfloat162float(aw[1]);
            v.z += __bfloat162float(aw[2]); v.w += __bfloat162float(aw[3]);
        }
        bf162* o = (bf162*)(out + (size_t)(m0 + r) * ldo + n0 + c4);
        o[0] = cvt2(v.x, v.y); o[1] = cvt2(v.z, v.w);
    }
}

// ---------------- 128x256 vocab GEMM + fused LSE chunks (2 per block) ----------------
// 256 threads / 8 warps as 2(m) x 4(n); warp tile 64x64.
__global__ __launch_bounds__(256) void k_vocab256(const float* __restrict__ bias) {
    extern __shared__ __align__(16) char dyn[];
    __shared__ float sb[256];
    bf16* As = (bf16*)dyn;                     // 2 stages x 128 x 72
    bf16* Ws = (bf16*)dyn + 2 * V_ASTAGE;      // 2 stages x 256 x 72
    float* Cs = (float*)dyn;                   // epilogue alias: 128 x 132
    int tid = threadIdx.x;
    int wid = tid >> 5;
    int wm = (wid & 1) * 64, wn = (wid >> 1) * 64;
    int m0 = blockIdx.x * 128, n0 = blockIdx.y * 256;
    if (tid < 256) sb[tid] = bias[n0 + tid];

    const bf16* A = g_avallb + (size_t)m0 * DDH;
    const bf16* W = g_Wout + (size_t)n0 * DDH;

    wmma::fragment<wmma::accumulator, 16, 16, 16, float> acc[4][4];
#pragma unroll
    for (int i = 0; i < 4; i++)
#pragma unroll
        for (int j = 0; j < 4; j++) wmma::fill_fragment(acc[i][j], 0.f);

    // staging: A rows 128 (2 threads/row, 32-col halves); W rows 256 (1 thread/row, 64 cols)
    int r = tid >> 1, hc = (tid & 1) * 32;
    const bf16* Ap = A + (size_t)r * DDH + hc;
    const bf16* Wp = W + (size_t)tid * DDH;

    float4 a0 = *(const float4*)Ap;
    float4 a1 = *(const float4*)(Ap + 8);
    float4 a2 = *(const float4*)(Ap + 16);
    float4 a3 = *(const float4*)(Ap + 24);
    float4 w0 = *(const float4*)Wp;
    float4 w1 = *(const float4*)(Wp + 8);
    float4 w2 = *(const float4*)(Wp + 16);
    float4 w3 = *(const float4*)(Wp + 24);
    float4 w4 = *(const float4*)(Wp + 32);
    float4 w5 = *(const float4*)(Wp + 40);
    float4 w6 = *(const float4*)(Wp + 48);
    float4 w7 = *(const float4*)(Wp + 56);
    {
        uint32_t oa = (uint32_t)r * 72u + (uint32_t)hc;
        *(float4*)&As[oa] = a0; *(float4*)&As[oa + 8] = a1;
        *(float4*)&As[oa + 16] = a2; *(float4*)&As[oa + 24] = a3;
        uint32_t ow = (uint32_t)tid * 72u;
        *(float4*)&Ws[ow] = w0; *(float4*)&Ws[ow + 8] = w1;
        *(float4*)&Ws[ow + 16] = w2; *(float4*)&Ws[ow + 24] = w3;
        *(float4*)&Ws[ow + 32] = w4; *(float4*)&Ws[ow + 40] = w5;
        *(float4*)&Ws[ow + 48] = w6; *(float4*)&Ws[ow + 56] = w7;
    }

    const int niter = DDH >> 6;   // 16
    int cur = 0;
    for (int it = 0; it < niter; ++it) {
        __syncthreads();
        if (it + 1 < niter) {
            const bf16* Apn = Ap + (it + 1) * 64;
            const bf16* Wpn = Wp + (it + 1) * 64;
            a0 = *(const float4*)Apn;        a1 = *(const float4*)(Apn + 8);
            a2 = *(const float4*)(Apn + 16); a3 = *(const float4*)(Apn + 24);
            w0 = *(const float4*)Wpn;        w1 = *(const float4*)(Wpn + 8);
            w2 = *(const float4*)(Wpn + 16); w3 = *(const float4*)(Wpn + 24);
            w4 = *(const float4*)(Wpn + 32); w5 = *(const float4*)(Wpn + 40);
            w6 = *(const float4*)(Wpn + 48); w7 = *(const float4*)(Wpn + 56);
        }
        const bf16* Ab = As + cur * V_ASTAGE;
        const bf16* Wb = Ws + cur * V_WSTAGE;
#pragma unroll
        for (int kk = 0; kk < 64; kk += 16) {
            wmma::fragment<wmma::matrix_a, 16, 16, 16, bf16, wmma::row_major> af[4];
#pragma unroll
            for (int i = 0; i < 4; i++)
                wmma::load_matrix_sync(af[i], Ab + (wm + i * 16) * 72 + kk, 72);
#pragma unroll
            for (int j = 0; j < 4; j++) {
                wmma::fragment<wmma::matrix_b, 16, 16, 16, bf16, wmma::col_major> bfr;
                wmma::load_matrix_sync(bfr, Wb + (wn + j * 16) * 72 + kk, 72);
#pragma unroll
                for (int i = 0; i < 4; i++)
                    wmma::mma_sync(acc[i][j], af[i], bfr, acc[i][j]);
            }
        }
        if (it + 1 < niter) {
            int nb = cur ^ 1;
            uint32_t oa = (uint32_t)nb * V_ASTAGE * 2u / 2u;   // element offset
            oa = (uint32_t)nb * V_ASTAGE + (uint32_t)r * 72u + (uint32_t)hc;
            *(float4*)&As[oa] = a0; *(float4*)&As[oa + 8] = a1;
            *(float4*)&As[oa + 16] = a2; *(float4*)&As[oa + 24] = a3;
            uint32_t ow = (uint32_t)nb * V_WSTAGE + (uint32_t)tid * 72u;
            *(float4*)&Ws[ow] = w0; *(float4*)&Ws[ow + 8] = w1;
            *(float4*)&Ws[ow + 16] = w2; *(float4*)&Ws[ow + 24] = w3;
            *(float4*)&Ws[ow + 32] = w4; *(float4*)&Ws[ow + 40] = w5;
            *(float4*)&Ws[ow + 48] = w6; *(float4*)&Ws[ow + 56] = w7;
        }
        cur ^= 1;
    }

    // epilogue: two 128-col halves; per half store frags -> Cs, then per-row (max, sum)
#pragma unroll
    for (int half = 0; half < 2; half++) {
        __syncthreads();
        if ((wn < 128) == (half == 0)) {
            int wnl = wn - half * 128;
#pragma unroll
            for (int i = 0; i < 4; i++)
#pragma unroll
                for (int j = 0; j < 4; j++)
                    wmma::store_matrix_sync(Cs + (size_t)(wm + i * 16) * 132 + wnl + j * 16,
                                            acc[i][j], 132, wmma::mem_row_major);
        }
        __syncthreads();
        int row = tid >> 1, part = (tid & 1) * 64;
        int rg = m0 + row;
        const float* Cr = Cs + row * 132 + part;
        const float* bb = sb + half * 128 + part;
        float m = -1e30f;
#pragma unroll 8
        for (int c = 0; c < 64; c++) m = fmaxf(m, Cr[c] + bb[c]);
        float mn = fmaxf(m, __shfl_xor_sync(0xffffffffu, m, 1));
        float s = 0.f;
#pragma unroll 8
        for (int c = 0; c < 64; c++) s += __expf(Cr[c] + bb[c] - mn);
        s += __shfl_xor_sync(0xffffffffu, s, 1);
        if (rg < MR) {
            if ((tid & 1) == 0) {
                size_t co = ((size_t)rg * NTV + blockIdx.y * 2 + half) * 2;
                g_chunk[co + 0] = mn;
                g_chunk[co + 1] = s;
            }
            int loc = g_goldtok[rg] - n0 - half * 128 - part;
            if (loc >= 0 && loc < 64) g_gold[rg] = Cr[loc] + bb[loc];
        }
    }
}

// ---------------- persistent encoder: 64 steps ----------------
__global__ __launch_bounds__(256, 2) void k_enc_persist(
    const bf16* __restrict__ Wf, const bf16* __restrict__ Wr)
{
    extern __shared__ __align__(16) char dyn[];
    float* Cs = (float*)dyn;
    unsigned gen = 0;
    int p = blockIdx.x, tid = threadIdx.x;
    int d = p >> 4;
    int n0 = (p & 15) * 128;
    const bf16* A = g_hsb + d * (BB * HH);
    const bf16* W = (d ? Wr : Wf) + (size_t)n0 * HH;
    const float* pre_base = d ? g_Gr : g_Gf;
    for (int t = 0; t < TSR; t++) {
        gemm_core(A, HH, W, HH, HH, dyn, Cs, 136);
        for (int it = tid; it < 2048; it += 256) {
            int b = it >> 5, jl = it & 31;
            const float* cr = Cs + b * 136 + 4 * jl;
            const float* pre = pre_base + (size_t)(b * TSR + t) * 2048 + n0 + 4 * jl;
            float gi = cr[0] + pre[0];
            float gf = cr[1] + pre[1];
            float gg = cr[2] + pre[2];
            float go = cr[3] + pre[3];
            int j = (n0 >> 2) + jl;
            int si = d * (BB * HH) + (b << 9) + j;
            float c = sigf(gf) * g_cs[si] + sigf(gi) * tanhf(gg);
            float h = sigf(go) * tanhf(c);
            g_cs[si] = c;
            g_hsb[si] = __float2bfloat16(h);
            size_t o = (size_t)(b * TSR + t) * 1024 + d * 512 + j;
            g_Henc[o] = h; g_Cenc[o] = c; g_Hencb[o] = __float2bfloat16(h);
        }
        gsync(0, NBE, gen);
    }
}

// ---------------- persistent decoder: 63 steps, 2 phases/step ----------------
__global__ __launch_bounds__(256, 2) void k_dec_persist(const int* __restrict__ src_lens) {
    extern __shared__ __align__(16) char dyn[];
    float* Cs = (float*)dyn;
    unsigned gen = 0;
    int p = blockIdx.x, tid = threadIdx.x;
    for (int t = 0; t < TD; t++) {
        // ---- Phase A ----
        if (p < 128) {
            int nt = p & 31, ks = p >> 5;
            const bf16* A = g_hb + ks * 256;
            const bf16* W; int ldw;
            if (t == 0) { W = g_WdecR + (size_t)(nt * 128) * 2048 + 1024 + ks * 256; ldw = 2048; }
            else        { W = g_Wgate + (size_t)(nt * 128) * 1024 + ks * 256; ldw = 1024; }
            gemm_core(A, 1024, W, ldw, 256, dyn,
                      g_Pg + (size_t)ks * (64 * 4096) + nt * 128, 4096);
        } else if (t > 0) {
            int q = p - 128, b = q >> 1;
            float* sps = Cs;                         // 64 floats
            if (tid < 64) sps[tid] = g_spg[b * 64 + tid];
            __syncthreads();
            int c0 = (q & 1) * 2048 + tid * 8;
            float acc[8];
#pragma unroll
            for (int i = 0; i < 8; i++) acc[i] = 0.f;
            const bf16* Hc0 = g_HencC + (size_t)(b * 64) * 4096 + c0;
            for (int u = 0; u < 64; u++) {
                float pw = sps[u];
                float4 r0 = *(const float4*)(Hc0 + (size_t)u * 4096);
                const bf162* pp = (const bf162*)&r0;
#pragma unroll
                for (int i = 0; i < 4; i++) {
                    float2 f = __bfloat1622float2(pp[i]);
                    acc[2 * i] += pw * f.x; acc[2 * i + 1] += pw * f.y;
                }
            }
            float* cgw = g_ctxg + (size_t)b * 4096 + c0;
            *(float4*)cgw       = make_float4(acc[0], acc[1], acc[2], acc[3]);
            *(float4*)(cgw + 4) = make_float4(acc[4], acc[5], acc[6], acc[7]);
            __syncthreads();
        }
        gsync(4, NBD, gen);
        // ---- Phase B ----
        if (p < 64) {
            int b = p;
            float* sh = Cs;            // 1024
            float* sc = Cs + 1024;     // 64
            float* sp = Cs + 1088;     // 64
            const float* pre = g_Gdec + (size_t)((t << 6) + b) * 4096;
            const float* P0 = g_Pg + (size_t)b * 4096;
            const float* cg = g_ctxg + (size_t)b * 4096;
#pragma unroll
            for (int u = 0; u < 4; u++) {
                int j = tid + u * 256;
                int col = 4 * j;
                float4 gp = *(const float4*)(pre + col);
                float4 q0 = *(const float4*)(P0 + col);
                float4 q1 = *(const float4*)(P0 + 64 * 4096 + col);
                float4 q2 = *(const float4*)(P0 + 2 * 64 * 4096 + col);
                float4 q3 = *(const float4*)(P0 + 3 * 64 * 4096 + col);
                float gi = gp.x + q0.x + q1.x + q2.x + q3.x;
                float gf = gp.y + q0.y + q1.y + q2.y + q3.y;
                float gg = gp.z + q0.z + q1.z + q2.z + q3.z;
                float go = gp.w + q0.w + q1.w + q2.w + q3.w;
                if (t > 0) {
                    float4 ca = *(const float4*)(g_constA + col);
                    float4 cx = *(const float4*)(cg + col);
                    gi += ca.x + cx.x; gf += ca.y + cx.y;
                    gg += ca.z + cx.z; go += ca.w + cx.w;
                }
                int ci = (b << 10) + j;
                float c = sigf(gf) * g_c[ci] + sigf(gi) * tanhf(gg);
                float h = sigf(go) * tanhf(c);
                g_c[ci] = c;
                sh[j] = h;
                bf16 hb = __float2bfloat16(h);
                g_hb[ci] = hb;
                g_yall[(size_t)((t << 6) + b) * 2048 + j] = hb;
            }
            __syncthreads();
            // attention scores
            {
                int tt = tid >> 2, q = tid & 3;
                const bf162* He = (const bf162*)(g_Hencb + (size_t)(b * TSR + tt) * 1024 + q * 256);
                const float* hh = sh + q * 256;
                float s = 0.f;
#pragma unroll 8
                for (int j = 0; j < 128; j++) {
                    bf162 v = He[j];
                    s += hh[2 * j] * __bfloat162float(v.x) + hh[2 * j + 1] * __bfloat162float(v.y);
                }
                s += __shfl_xor_sync(0xffffffffu, s, 1);
                s += __shfl_xor_sync(0xffffffffu, s, 2);
                if (q == 0) sc[tt] = s;
            }
            __syncthreads();
            int L = src_lens[b];
            float m = -1e30f;
            for (int u = 0; u < 64; u++) if (u < L) m = fmaxf(m, sc[u]);
            float den = 0.f;
            for (int u = 0; u < 64; u++) if (u < L) den += __expf(sc[u] - m);
            if (tid < 64) {
                float pv = (tid < L) ? (__expf(sc[tid] - m) / den) : 0.f;
                sp[tid] = pv;
                g_spg[b * 64 + tid] = pv;
            }
            __syncthreads();
            // ctx (1024) -> yall[..., 1024:2048]
            {
                int j0 = tid * 4;
                float a0 = 0.f, a1 = 0.f, a2 = 0.f, a3 = 0.f;
                for (int u = 0; u < L; u++) {
                    float pw = sp[u];
                    const bf162* Hr = (const bf162*)(g_Hencb + (size_t)(b * TSR + u) * 1024 + j0);
                    bf162 v0 = Hr[0], v1 = Hr[1];
                    a0 += pw * __bfloat162float(v0.x); a1 += pw * __bfloat162float(v0.y);
                    a2 += pw * __bfloat162float(v1.x); a3 += pw * __bfloat162float(v1.y);
                }
                bf162* co = (bf162*)(g_yall + (size_t)((t << 6) + b) * 2048 + 1024 + j0);
                co[0] = cvt2(a0, a1); co[1] = cvt2(a2, a3);
            }
        }
        gsync(4, NBD, gen);
    }
}

// ---------------- decoder init (fp32 path, one-time) ----------------
__global__ void k_final(const int* __restrict__ src_lens) {
    int i = blockIdx.x * blockDim.x + threadIdx.x;    // < 64*2048
    int b = i >> 11, j = i & 2047;
    int last = src_lens[b] - 1;
    size_t o = (size_t)(b * TSR + last) * 1024;
    g_final[i] = (j < 1024) ? g_Henc[o + j] : g_Cenc[o + j - 1024];
}

__global__ void k_sgemm_init(const float* __restrict__ W) {
    __shared__ float As[16][64];
    __shared__ float Ws[16][32];
    int z = blockIdx.z;
    int koff = z * 512;
    int tid = threadIdx.x;
    int n0 = blockIdx.x * 32;
    int ty = tid >> 3, tx = tid & 7;
    int lr = tid >> 1, lc = (tid & 1) * 8;
    int wr = tid >> 2, wc = (tid & 3) * 4;
    float acc[4][4];
#pragma unroll
    for (int i = 0; i < 4; i++)
#pragma unroll
        for (int j = 0; j < 4; j++) acc[i][j] = 0.f;
    const float* Ab = g_final + (size_t)lr * 2048 + koff + lc;
    const float* Wb = W + (size_t)(n0 + wr) * 2048 + koff + wc;
    for (int k0 = 0; k0 < 512; k0 += 16) {
        float4 a0 = *(const float4*)(Ab + k0);
        float4 a1 = *(const float4*)(Ab + k0 + 4);
        float4 b0 = *(const float4*)(Wb + k0);
        __syncthreads();
        As[lc + 0][lr] = a0.x; As[lc + 1][lr] = a0.y; As[lc + 2][lr] = a0.z; As[lc + 3][lr] = a0.w;
        As[lc + 4][lr] = a1.x; As[lc + 5][lr] = a1.y; As[lc + 6][lr] = a1.z; As[lc + 7][lr] = a1.w;
        Ws[wc + 0][wr] = b0.x; Ws[wc + 1][wr] = b0.y; Ws[wc + 2][wr] = b0.z; Ws[wc + 3][wr] = b0.w;
        __syncthreads();
#pragma unroll
        for (int kk = 0; kk < 16; kk++) {
            float a[4], b[4];
#pragma unroll
            for (int i = 0; i < 4; i++) a[i] = As[kk][ty * 4 + i];
#pragma unroll
            for (int j = 0; j < 4; j++) b[j] = Ws[kk][tx * 4 + j];
#pragma unroll
            for (int i = 0; i < 4; i++)
#pragma unroll
                for (int j = 0; j < 4; j++) acc[i][j] += a[i] * b[j];
        }
    }
    float* Pz = g_Phid + (size_t)z * (BB * DDH);
#pragma unroll
    for (int i = 0; i < 4; i++)
#pragma unroll
        for (int j = 0; j < 4; j++)
            Pz[(ty * 4 + i) * DDH + n0 + tx * 4 + j] = acc[i][j];
}

__global__ void k_init(const float* __restrict__ init_b) {
    int i = blockIdx.x * blockDim.x + threadIdx.x;    // < 64*1024
    int j = i & 1023;
    float c = init_b[j];
#pragma unroll
    for (int s = 0; s < 4; s++) c += g_Phid[s * (BB * DDH) + i];
    g_c[i] = c;
    g_hb[i] = __float2bfloat16(tanhf(c));
}

// ---------------- per-row LSE combine + masked sum ----------------
__global__ void k_rowlse() {
    int tid = threadIdx.x;                 // 256
    int b = tid >> 2, q = tid & 3;
    int row = blockIdx.x * 64 + b;
    const float* ch = g_chunk + (size_t)row * NTV * 2;
    float m = -1e30f;
    for (int i = q; i < NTV; i += 4) m = fmaxf(m, ch[2 * i]);
    m = fmaxf(m, __shfl_xor_sync(0xffffffffu, m, 1));
    m = fmaxf(m, __shfl_xor_sync(0xffffffffu, m, 2));
    float s = 0.f;
    for (int i = q; i < NTV; i += 4) s += ch[2 * i + 1] * __expf(ch[2 * i] - m);
    s += __shfl_xor_sync(0xffffffffu, s, 1);
    s += __shfl_xor_sync(0xffffffffu, s, 2);
    if (q == 0) {
        float lse = m + logf(s);
        g_rowval[row] = (g_gold[row] - lse) * g_maskf[row];
    }
}

__global__ void k_sum(float* __restrict__ out) {
    __shared__ float sm[256];
    int tid = threadIdx.x;
    float s = 0.f;
    for (int i = tid; i < MR; i += 256) s += g_rowval[i];
    sm[tid] = s;
    __syncthreads();
    for (int st = 128; st > 0; st >>= 1) {
        if (tid < st) sm[tid] += sm[tid + st];
        __syncthreads();
    }
    if (tid == 0) out[0] = sm[0];
}

// ---------------- launch ----------------
extern "C" void kernel_launch(void* const* d_in, const int* in_sizes, int n_in,
                              void* d_out, int out_size) {
    (void)in_sizes; (void)n_in; (void)out_size;
    const int*   src_tokens = (const int*)d_in[0];
    const int*   src_lens   = (const int*)d_in[1];
    const int*   trg_tokens = (const int*)d_in[2];
    const int*   trg_lens   = (const int*)d_in[3];
    const float* src_emb    = (const float*)d_in[4];
    const float* trg_emb    = (const float*)d_in[5];
    const float* enc_Wih    = (const float*)d_in[6];
    const float* enc_Whh    = (const float*)d_in[7];
    const float* enc_b      = (const float*)d_in[8];
    const float* rev_Wih    = (const float*)d_in[9];
    const float* rev_Whh    = (const float*)d_in[10];
    const float* rev_b      = (const float*)d_in[11];
    const float* dec_Wih    = (const float*)d_in[12];
    const float* dec_Whh    = (const float*)d_in[13];
    const float* dec_b      = (const float*)d_in[14];
    const float* hid_W      = (const float*)d_in[15];
    const float* hid_b      = (const float*)d_in[16];
    const float* out_W      = (const float*)d_in[17];
    const float* out_b      = (const float*)d_in[18];
    const float* init_W     = (const float*)d_in[19];
    const float* init_b     = (const float*)d_in[20];

    bf16 *p_svb, *p_tvb, *p_Wencf, *p_Wencr, *p_Whhf, *p_Whhr, *p_WdecE, *p_WhidB,
         *p_Wout, *p_WhidLT, *p_WhidRT, *p_Wgate, *p_WcombC, *p_HencC, *p_Hencb,
         *p_WdecR, *p_yall, *p_avallb;
    float *p_Gf, *p_Gr, *p_Gdec, *p_bencf, *p_bencr, *p_bdec;
    cudaGetSymbolAddress((void**)&p_svb, g_svb);
    cudaGetSymbolAddress((void**)&p_tvb, g_tvb);
    cudaGetSymbolAddress((void**)&p_Wencf, g_WencfP);
    cudaGetSymbolAddress((void**)&p_Wencr, g_WencrP);
    cudaGetSymbolAddress((void**)&p_Whhf, g_WhhfP);
    cudaGetSymbolAddress((void**)&p_Whhr, g_WhhrP);
    cudaGetSymbolAddress((void**)&p_WdecE, g_WdecE);
    cudaGetSymbolAddress((void**)&p_WhidB, g_WhidB);
    cudaGetSymbolAddress((void**)&p_Wout, g_Wout);
    cudaGetSymbolAddress((void**)&p_WhidLT, g_WhidLT);
    cudaGetSymbolAddress((void**)&p_WhidRT, g_WhidRT);
    cudaGetSymbolAddress((void**)&p_Wgate, g_Wgate);
    cudaGetSymbolAddress((void**)&p_WcombC, g_WcombC);
    cudaGetSymbolAddress((void**)&p_HencC, g_HencC);
    cudaGetSymbolAddress((void**)&p_Hencb, g_Hencb);
    cudaGetSymbolAddress((void**)&p_WdecR, g_WdecR);
    cudaGetSymbolAddress((void**)&p_yall, g_yall);
    cudaGetSymbolAddress((void**)&p_avallb, g_avallb);
    cudaGetSymbolAddress((void**)&p_Gf, g_Gf);
    cudaGetSymbolAddress((void**)&p_Gr, g_Gr);
    cudaGetSymbolAddress((void**)&p_Gdec, g_Gdec);
    cudaGetSymbolAddress((void**)&p_bencf, g_bencfP);
    cudaGetSymbolAddress((void**)&p_bencr, g_bencrP);
    cudaGetSymbolAddress((void**)&p_bdec, g_bdecP);

    // dynamic smem opt-in
    cudaFuncSetAttribute(k_ff128, cudaFuncAttributeMaxDynamicSharedMemorySize, DYN2);
    cudaFuncSetAttribute(k_gemm128_b, cudaFuncAttributeMaxDynamicSharedMemorySize, DYN2);
    cudaFuncSetAttribute(k_vocab256, cudaFuncAttributeMaxDynamicSharedMemorySize, DYN3);
    cudaFuncSetAttribute(k_enc_persist, cudaFuncAttributeMaxDynamicSharedMemorySize, DYN_SMEM);
    cudaFuncSetAttribute(k_dec_persist, cudaFuncAttributeMaxDynamicSharedMemorySize, DYN_SMEM);

    k_zero_state<<<256, 256>>>();
    k_zeropad<<<512, 256>>>();
    k_gather_src<<<BB * TSR, 128>>>(src_tokens, src_emb);
    k_gather_trg<<<MR, 128>>>(trg_tokens, trg_lens, trg_emb);

    // weight conversions + gate-interleave permutations
    k_permW512<<<2048, 128>>>(enc_Wih, p_Wencf, 512, 512);
    k_permW512<<<2048, 128>>>(rev_Wih, p_Wencr, 512, 512);
    k_permW512<<<2048, 128>>>(enc_Whh, p_Whhf, 512, 512);
    k_permW512<<<2048, 128>>>(rev_Whh, p_Whhr, 512, 512);
    k_permW512<<<4096, 128>>>(dec_Wih, p_WdecE, 1024, 1536);
    k_permDecR<<<4096, 256>>>(dec_Wih, dec_Whh);
    k_permB<<<8, 256>>>(enc_b, p_bencf, 512);
    k_permB<<<8, 256>>>(rev_b, p_bencr, 512);
    k_permB<<<16, 256>>>(dec_b, p_bdec, 1024);
    k_f2b<<<(DDH * 2048 / 4 + 255) / 256, 256>>>(hid_W, p_WhidB, DDH * 2048 / 4);
    k_f2b<<<(VOC * DDH / 4 + 255) / 256, 256>>>(out_W, p_Wout, VOC * DDH / 4);
    k_transpose_hid<<<dim3(32, 32, 2), dim3(32, 8)>>>(hid_W);
    k_const<<<512, 256>>>(hid_b);

    // composed decoder weights: Wgate = WA@WhidL + Whh ; WcombC = WA@WhidR
    k_gemm128_b<<<dim3(32, 8), 256, DYN2>>>(p_WdecR, 2048, p_WhidLT, 1024, 1024,
                                            (const float*)0, p_WdecR + 1024, 2048,
                                            p_Wgate, 1024);
    k_gemm128_b<<<dim3(32, 8), 256, DYN2>>>(p_WdecR, 2048, p_WhidRT, 1024, 1024,
                                            (const float*)0, (const bf16*)0, 0,
                                            p_WcombC, 1024);

    // input projections (tensor cores, interleaved outputs)
    k_ff128<<<dim3(32, 16), 256, DYN2>>>(p_svb, EE, p_Wencf, EE, p_bencf, p_Gf, 2048, EE);
    k_ff128<<<dim3(32, 16), 256, DYN2>>>(p_svb, EE, p_Wencr, EE, p_bencr, p_Gr, 2048, EE);
    k_ff128<<<dim3(32, 32), 256, DYN2>>>(p_tvb, EE, p_WdecE, EE, p_bdec, p_Gdec, 4096, EE);

    // encoder recurrence (persistent)
    k_enc_persist<<<NBE, 256, DYN_SMEM>>>(p_Whhf, p_Whhr);

    // HencC = Henc @ WcombC^T  (needs encoder output)
    k_gemm128_b<<<dim3(32, 32), 256, DYN2>>>(p_Hencb, 1024, p_WcombC, 1024, 1024,
                                             (const float*)0, (const bf16*)0, 0,
                                             p_HencC, 4096);

    // decoder init state
    k_final<<<512, 256>>>(src_lens);
    k_sgemm_init<<<dim3(32, 1, 4), 128>>>(init_W);
    k_init<<<256, 256>>>(init_b);

    // decoder recurrence (persistent, 2 phases/step)
    k_dec_persist<<<NBD, 256, DYN_SMEM>>>(src_lens);

    // deferred hid GEMM: avall = [h|ctx] @ hid_W^T + hid_b
    k_gemm128_b<<<dim3(32, 8), 256, DYN2>>>(p_yall, 2048, p_WhidB, 2048, 2048,
                                            hid_b, (const bf16*)0, 0, p_avallb, 1024);

    // vocab projection + LSE (128x256 tile, bias fused into LSE)
    k_vocab256<<<dim3(32, 125), 256, DYN3>>>(out_b);
    k_rowlse<<<63, 256>>>();
    k_sum<<<1, 256>>>((float*)d_out);
}

// round 14
// speedup vs baseline: 1.0243x; 1.0125x over previous
#include <cuda_runtime.h>
#include <cuda_bf16.h>
#include <mma.h>
#include <math.h>
#include <stdint.h>
using namespace nvcuda;

// ---------------- problem constants ----------------
#define BB   64      // batch
#define TSR  64      // src len
#define TTR  64      // trg len
#define EE   512     // embedding
#define HH   512     // encoder hidden per dir
#define DDH  1024    // decoder hidden
#define VOC  32000
#define TD   63              // decode steps
#define MR   (TD*BB)         // 4032 rows
#define MRP  4096            // padded row count for 128-tiles
#define NTV  (VOC/128)       // 250 column tiles of vocab
#define NBE  32              // encoder persistent grid
#define NBD  256             // decoder persistent grid

#define AS_STAGE (64*72)
#define WS_STAGE (128*72)
#define DYN_SMEM ((2*AS_STAGE + 2*WS_STAGE) * 2)   // 55296 bytes (64x128 core)

#define G128_STAGE (128*72)                         // bf16 elems per tensor per stage
#define DYN2 (4*G128_STAGE*2)                       // 73728 bytes (128x128 core)

typedef __nv_bfloat16 bf16;
typedef __nv_bfloat162 bf162;

// ---------------- static device scratch ----------------
__device__ bf16 g_svb  [BB*TSR*EE];       // src embedded bf16, row = b*TSR+t
__device__ bf16 g_tvb  [MRP*EE];          // trg embedded bf16, row = t*BB+b (padded)
__device__ bf16 g_WencfP[4*HH*EE];        // enc_Wih bf16, gate-interleaved rows
__device__ bf16 g_WencrP[4*HH*EE];
__device__ bf16 g_WhhfP [4*HH*HH];        // enc_Whh bf16 interleaved
__device__ bf16 g_WhhrP [4*HH*HH];
__device__ bf16 g_WdecE [4*DDH*EE];       // dec_Wih[:, :512] interleaved
__device__ bf16 g_WdecR [4*DDH*2048];     // [dec_Wih[:,512:1536] | dec_Whh] interleaved
__device__ bf16 g_WhidB [DDH*2*DDH];      // hid_W bf16 plain [1024][2048]
__device__ bf16 g_WhidLT[DDH*DDH];        // hid_W left half transposed  [k][j]
__device__ bf16 g_WhidRT[DDH*DDH];        // hid_W right half transposed [k][j]
__device__ bf16 g_Wgate [4*DDH*DDH];      // WA@WhidL + Whh (interleaved rows)
__device__ bf16 g_WcombC[4*DDH*DDH];      // WA@WhidR (interleaved rows)
__device__ bf16 g_HencC [BB*TSR*4*DDH];   // Henc @ WcombC^T  [(b*64+u)][4096]
__device__ bf16 g_Wout  [VOC*DDH];        // out_W bf16 plain
__device__ bf16 g_avallb[MRP*DDH];        // all av rows bf16 (padded)
__device__ bf16 g_yall  [MRP*2048];       // [h|ctx] rows (padded)

__device__ float g_bencfP[4*HH];          // permuted biases (fp32)
__device__ float g_bencrP[4*HH];
__device__ float g_bdecP [4*DDH];
__device__ float g_constA[4*DDH];         // WA_P @ hid_b

__device__ float g_Gf   [BB*TSR*4*HH];    // enc fwd preact (interleaved cols)
__device__ float g_Gr   [BB*TSR*4*HH];
__device__ float g_Gdec [MRP*4*DDH];      // dec preact (emb part + bias, interleaved)
__device__ float g_Henc [BB*TSR*2*HH];    // fp32 (for final-state gather)
__device__ float g_Cenc [BB*TSR*2*HH];
__device__ bf16  g_Hencb[BB*TSR*2*HH];    // bf16 copy for attention / HencC GEMM
__device__ bf16  g_hsb  [2*BB*HH];        // enc running h bf16 (both dirs)
__device__ float g_cs   [2*BB*HH];        // enc running c fp32
__device__ float g_c    [BB*DDH];         // dec c fp32
__device__ bf16  g_hb   [BB*DDH];         // dec h bf16 (gates GEMM input)
__device__ float g_ctxg [BB*4*DDH];       // ctx-contribution to next gates (fp32)
__device__ float g_spg  [BB*64];          // softmax probs (global, for ctxg blocks)
__device__ float g_Pg   [4*BB*4*DDH];     // gates split-K partials (4 x [64,4096])
__device__ float g_Phid [4*BB*DDH];       // init-GEMM split-K partials
__device__ float g_final[BB*2*DDH];       // concat(Henc,Cenc) at last
__device__ float g_chunk[MR*NTV*2];       // per-tile (max, sumexp)
__device__ float g_gold [MR];
__device__ int   g_goldtok[MR];
__device__ float g_maskf[MR];
__device__ float g_rowval[MR];
__device__ unsigned g_bar[8];             // encoder barrier: [0]=cnt [1]=gen
__device__ unsigned g_bar2[16];           // decoder barrier: [0..7]=sub, [8]=master, [9]=gen

__device__ __forceinline__ float sigf(float x) { return 1.0f / (1.0f + expf(-x)); }
__device__ __forceinline__ bf162 cvt2(float a, float b) {
    return __float22bfloat162_rn(make_float2(a, b));
}

// ---------------- device-wide software barriers ----------------
// simple barrier (encoder, 32 blocks)
__device__ __forceinline__ void gsync(int base, unsigned nb, unsigned& mygen) {
    __threadfence();
    __syncthreads();
    if (threadIdx.x == 0) {
        unsigned g = mygen;
        if (atomicAdd(&g_bar[base], 1u) == nb - 1u) {
            atomicExch(&g_bar[base], 0u);
            __threadfence();
            atomicExch(&g_bar[base + 1], g + 1u);
        } else {
            volatile unsigned* vg = (volatile unsigned*)&g_bar[base + 1];
            while (*vg == g) __nanosleep(64);
        }
    }
    mygen++;
    __syncthreads();
}

// hierarchical barrier (decoder, NBD blocks, NBD % 8 == 0):
// arrivals spread over 8 sub-counters (8 L2 addresses), last of each sub
// arrives on master, last master releases via generation word.
__device__ __forceinline__ void gsyncH(unsigned nb, unsigned& mygen) {
    __threadfence();
    __syncthreads();
    if (threadIdx.x == 0) {
        unsigned g = mygen;
        unsigned sub = blockIdx.x & 7u;
        unsigned quota = nb >> 3;
        bool released = false;
        if (atomicAdd(&g_bar2[sub], 1u) == quota - 1u) {
            atomicExch(&g_bar2[sub], 0u);
            if (atomicAdd(&g_bar2[8], 1u) == 7u) {
                atomicExch(&g_bar2[8], 0u);
                __threadfence();
                atomicExch(&g_bar2[9], g + 1u);
                released = true;
            }
        }
        if (!released) {
            volatile unsigned* vg = (volatile unsigned*)&g_bar2[9];
            while (*vg == g) __nanosleep(64);
        }
    }
    mygen++;
    __syncthreads();
}

// ============ 64x128 GEMM core (persistent kernels), K-tile 64 ============
__device__ __forceinline__ void gemm_core(
    const bf16* __restrict__ A, int lda,
    const bf16* __restrict__ W, int ldw,
    int K, char* smem, float* out, int ldo)
{
    bf16* As = (bf16*)smem;                  // 2 stages x 64 x 72
    bf16* Ws = (bf16*)smem + 2 * AS_STAGE;   // 2 stages x 128 x 72
    int tid = threadIdx.x;
    int wid = tid >> 5;
    int wr = (wid & 1) * 32, wc = (wid >> 1) * 32;

    wmma::fragment<wmma::accumulator, 16, 16, 16, float> acc[2][2];
#pragma unroll
    for (int i = 0; i < 2; i++)
#pragma unroll
        for (int j = 0; j < 2; j++) wmma::fill_fragment(acc[i][j], 0.f);

    int ar = tid >> 2, ac = (tid & 3) * 16;
    int wq = tid >> 1, wz = (tid & 1) * 32;
    const bf16* Ap = A + (size_t)ar * lda + ac;
    const bf16* Wp = W + (size_t)wq * ldw + wz;

    float4 a0 = *(const float4*)Ap;
    float4 a1 = *(const float4*)(Ap + 8);
    float4 w0 = *(const float4*)Wp;
    float4 w1 = *(const float4*)(Wp + 8);
    float4 w2 = *(const float4*)(Wp + 16);
    float4 w3 = *(const float4*)(Wp + 24);
    *(float4*)&As[ar * 72 + ac]     = a0;
    *(float4*)&As[ar * 72 + ac + 8] = a1;
    *(float4*)&Ws[wq * 72 + wz]      = w0;
    *(float4*)&Ws[wq * 72 + wz + 8]  = w1;
    *(float4*)&Ws[wq * 72 + wz + 16] = w2;
    *(float4*)&Ws[wq * 72 + wz + 24] = w3;

    int niter = K >> 6;
    int cur = 0;
    for (int it = 0; it < niter; ++it) {
        __syncthreads();
        if (it + 1 < niter) {
            const bf16* Apn = Ap + (it + 1) * 64;
            const bf16* Wpn = Wp + (it + 1) * 64;
            a0 = *(const float4*)Apn;
            a1 = *(const float4*)(Apn + 8);
            w0 = *(const float4*)Wpn;
            w1 = *(const float4*)(Wpn + 8);
            w2 = *(const float4*)(Wpn + 16);
            w3 = *(const float4*)(Wpn + 24);
        }
        const bf16* Ab = As + cur * AS_STAGE;
        const bf16* Wb = Ws + cur * WS_STAGE;
#pragma unroll
        for (int kk = 0; kk < 64; kk += 16) {
            wmma::fragment<wmma::matrix_a, 16, 16, 16, bf16, wmma::row_major> af[2];
            wmma::fragment<wmma::matrix_b, 16, 16, 16, bf16, wmma::col_major> bfr[2];
            wmma::load_matrix_sync(af[0], Ab + wr * 72 + kk, 72);
            wmma::load_matrix_sync(af[1], Ab + (wr + 16) * 72 + kk, 72);
            wmma::load_matrix_sync(bfr[0], Wb + wc * 72 + kk, 72);
            wmma::load_matrix_sync(bfr[1], Wb + (wc + 16) * 72 + kk, 72);
#pragma unroll
            for (int i = 0; i < 2; i++)
#pragma unroll
                for (int j = 0; j < 2; j++)
                    wmma::mma_sync(acc[i][j], af[i], bfr[j], acc[i][j]);
        }
        if (it + 1 < niter) {
            int nb = cur ^ 1;
            *(float4*)&As[nb * AS_STAGE + ar * 72 + ac]     = a0;
            *(float4*)&As[nb * AS_STAGE + ar * 72 + ac + 8] = a1;
            *(float4*)&Ws[nb * WS_STAGE + wq * 72 + wz]      = w0;
            *(float4*)&Ws[nb * WS_STAGE + wq * 72 + wz + 8]  = w1;
            *(float4*)&Ws[nb * WS_STAGE + wq * 72 + wz + 16] = w2;
            *(float4*)&Ws[nb * WS_STAGE + wq * 72 + wz + 24] = w3;
        }
        cur ^= 1;
    }
    __syncthreads();
#pragma unroll
    for (int i = 0; i < 2; i++)
#pragma unroll
        for (int j = 0; j < 2; j++)
            wmma::store_matrix_sync(out + (size_t)(wr + i * 16) * ldo + wc + j * 16,
                                    acc[i][j], ldo, wmma::mem_row_major);
    __syncthreads();
}

// ============ 128x128 GEMM core (feed-forward), warp tile 32x64 ============
__device__ __forceinline__ void gemm128(
    const bf16* __restrict__ A, int lda,
    const bf16* __restrict__ W, int ldw,
    int K, char* smem, float* out, int ldo)
{
    bf16* As = (bf16*)smem;                     // 2 stages x 128 x 72
    bf16* Ws = (bf16*)smem + 2 * G128_STAGE;    // 2 stages x 128 x 72
    int tid = threadIdx.x;
    int wid = tid >> 5;
    int wm = (wid & 3) * 32, wn = (wid >> 2) * 64;

    wmma::fragment<wmma::accumulator, 16, 16, 16, float> acc[2][4];
#pragma unroll
    for (int i = 0; i < 2; i++)
#pragma unroll
        for (int j = 0; j < 4; j++) wmma::fill_fragment(acc[i][j], 0.f);

    int r = tid >> 1, hc = (tid & 1) * 32;
    const bf16* Ap = A + (size_t)r * lda + hc;
    const bf16* Wp = W + (size_t)r * ldw + hc;

    float4 a0 = *(const float4*)Ap;
    float4 a1 = *(const float4*)(Ap + 8);
    float4 a2 = *(const float4*)(Ap + 16);
    float4 a3 = *(const float4*)(Ap + 24);
    float4 w0 = *(const float4*)Wp;
    float4 w1 = *(const float4*)(Wp + 8);
    float4 w2 = *(const float4*)(Wp + 16);
    float4 w3 = *(const float4*)(Wp + 24);
    {
        uint32_t o = (uint32_t)r * 72u + (uint32_t)hc;
        *(float4*)&As[o] = a0; *(float4*)&As[o + 8] = a1;
        *(float4*)&As[o + 16] = a2; *(float4*)&As[o + 24] = a3;
        *(float4*)&Ws[o] = w0; *(float4*)&Ws[o + 8] = w1;
        *(float4*)&Ws[o + 16] = w2; *(float4*)&Ws[o + 24] = w3;
    }

    int niter = K >> 6;
    int cur = 0;
    for (int it = 0; it < niter; ++it) {
        __syncthreads();
        if (it + 1 < niter) {
            const bf16* Apn = Ap + (it + 1) * 64;
            const bf16* Wpn = Wp + (it + 1) * 64;
            a0 = *(const float4*)Apn;       a1 = *(const float4*)(Apn + 8);
            a2 = *(const float4*)(Apn + 16); a3 = *(const float4*)(Apn + 24);
            w0 = *(const float4*)Wpn;       w1 = *(const float4*)(Wpn + 8);
            w2 = *(const float4*)(Wpn + 16); w3 = *(const float4*)(Wpn + 24);
        }
        const bf16* Ab = As + cur * G128_STAGE;
        const bf16* Wb = Ws + cur * G128_STAGE;
#pragma unroll
        for (int kk = 0; kk < 64; kk += 16) {
            wmma::fragment<wmma::matrix_a, 16, 16, 16, bf16, wmma::row_major> af[2];
            wmma::fragment<wmma::matrix_b, 16, 16, 16, bf16, wmma::col_major> bfr[4];
            wmma::load_matrix_sync(af[0], Ab + wm * 72 + kk, 72);
            wmma::load_matrix_sync(af[1], Ab + (wm + 16) * 72 + kk, 72);
#pragma unroll
            for (int j = 0; j < 4; j++)
                wmma::load_matrix_sync(bfr[j], Wb + (wn + j * 16) * 72 + kk, 72);
#pragma unroll
            for (int i = 0; i < 2; i++)
#pragma unroll
                for (int j = 0; j < 4; j++)
                    wmma::mma_sync(acc[i][j], af[i], bfr[j], acc[i][j]);
        }
        if (it + 1 < niter) {
            int nb = cur ^ 1;
            uint32_t o = (uint32_t)nb * G128_STAGE + (uint32_t)r * 72u + (uint32_t)hc;
            *(float4*)&As[o] = a0; *(float4*)&As[o + 8] = a1;
            *(float4*)&As[o + 16] = a2; *(float4*)&As[o + 24] = a3;
            *(float4*)&Ws[o] = w0; *(float4*)&Ws[o + 8] = w1;
            *(float4*)&Ws[o + 16] = w2; *(float4*)&Ws[o + 24] = w3;
        }
        cur ^= 1;
    }
    __syncthreads();
#pragma unroll
    for (int i = 0; i < 2; i++)
#pragma unroll
        for (int j = 0; j < 4; j++)
            wmma::store_matrix_sync(out + (size_t)(wm + i * 16) * ldo + wn + j * 16,
                                    acc[i][j], ldo, wmma::mem_row_major);
    __syncthreads();
}

// ---------------- conversions / permutations ----------------
__global__ void k_f2b(const float* __restrict__ x, bf16* __restrict__ y, int n4) {
    int i = blockIdx.x * blockDim.x + threadIdx.x;
    if (i < n4) {
        float4 v = ((const float4*)x)[i];
        ((bf162*)y)[2 * i]     = cvt2(v.x, v.y);
        ((bf162*)y)[2 * i + 1] = cvt2(v.z, v.w);
    }
}

__global__ void k_permW512(const float* __restrict__ W, bf16* __restrict__ out,
                           int J, int ldin) {
    int row = blockIdx.x;
    int j = row >> 2, g = row & 3;
    const float4* src = (const float4*)(W + (size_t)(g * J + j) * ldin);
    bf162* dst = (bf162*)(out + (size_t)row * 512);
    int t = threadIdx.x;                   // 128
    float4 v = src[t];
    dst[2 * t]     = cvt2(v.x, v.y);
    dst[2 * t + 1] = cvt2(v.z, v.w);
}

__global__ void k_permDecR(const float* __restrict__ Wih, const float* __restrict__ Whh) {
    int row = blockIdx.x;                  // 4096
    int j = row >> 2, g = row & 3;
    int t = threadIdx.x;                   // 256, 8 elems each
    const float* src = (t < 128)
        ? (Wih + (size_t)(g * 1024 + j) * 1536 + 512 + t * 8)
        : (Whh + (size_t)(g * 1024 + j) * 1024 + (t - 128) * 8);
    bf162* dst = (bf162*)(g_WdecR + (size_t)row * 2048 + t * 8);
    float4 a = *(const float4*)src;
    float4 b = *(const float4*)(src + 4);
    dst[0] = cvt2(a.x, a.y); dst[1] = cvt2(a.z, a.w);
    dst[2] = cvt2(b.x, b.y); dst[3] = cvt2(b.z, b.w);
}

__global__ void k_permB(const float* __restrict__ b, float* __restrict__ out, int J) {
    int i = blockIdx.x * blockDim.x + threadIdx.x;
    if (i < 4 * J) { int j = i >> 2, g = i & 3; out[i] = b[g * J + j]; }
}

// transpose hid_W halves -> bf16 [k][j]
__global__ void k_transpose_hid(const float* __restrict__ W) {
    __shared__ float tile[32][33];
    int half = blockIdx.z;
    int k0 = blockIdx.x * 32;
    int j0 = blockIdx.y * 32;
    int tx = threadIdx.x, ty = threadIdx.y;   // 32 x 8
#pragma unroll
    for (int i = 0; i < 32; i += 8)
        tile[ty + i][tx] = W[(size_t)(j0 + ty + i) * 2048 + half * 1024 + k0 + tx];
    __syncthreads();
    bf16* out = half ? g_WhidRT : g_WhidLT;
#pragma unroll
    for (int i = 0; i < 32; i += 8)
        out[(size_t)(k0 + ty + i) * 1024 + j0 + tx] = __float2bfloat16(tile[tx][ty + i]);
}

// constA[row] = dot(WA_P[row,:], hid_b)
__global__ void k_const(const float* __restrict__ hid_b) {
    int row = blockIdx.x * 8 + (threadIdx.x >> 5);
    int lane = threadIdx.x & 31;
    const bf16* wr = g_WdecR + (size_t)row * 2048;
    float s = 0.f;
    for (int k = lane; k < 1024; k += 32) s += __bfloat162float(wr[k]) * hid_b[k];
#pragma unroll
    for (int o = 16; o > 0; o >>= 1) s += __shfl_xor_sync(0xffffffffu, s, o);
    if (lane == 0) g_constA[row] = s;
}

// ---------------- init / gathers ----------------
__global__ void k_zero_state() {
    int i = blockIdx.x * blockDim.x + threadIdx.x;
    if (i < 2 * BB * HH) { g_cs[i] = 0.f; g_hsb[i] = __float2bfloat16(0.f); }
    if (i < 8) g_bar[i] = 0u;
    if (i < 16) g_bar2[i] = 0u;
}

// zero the pad rows (rows MR..MRP) of avall / tvb / yall
__global__ void k_zeropad() {
    int i = blockIdx.x * blockDim.x + threadIdx.x;
    bf16 z = __float2bfloat16(0.f);
    if (i < 64 * 1024) g_avallb[MR * DDH + i] = z;
    if (i < 64 * 512)  g_tvb[MR * EE + i] = z;
    if (i < 64 * 2048) g_yall[(size_t)MR * 2048 + i] = z;
}

__global__ void k_gather_src(const int* __restrict__ tok, const float* __restrict__ emb) {
    int r = blockIdx.x;
    int v = tok[r];
    float4 val = ((const float4*)(emb + (size_t)v * EE))[threadIdx.x];
    bf162* d = (bf162*)(g_svb + (size_t)r * EE + threadIdx.x * 4);
    d[0] = cvt2(val.x, val.y); d[1] = cvt2(val.z, val.w);
}

__global__ void k_gather_trg(const int* __restrict__ tok, const int* __restrict__ lens,
                             const float* __restrict__ emb) {
    int r = blockIdx.x;                    // t*BB + b
    int t = r >> 6, b = r & 63;
    int v = tok[b * TTR + t];
    float4 val = ((const float4*)(emb + (size_t)v * EE))[threadIdx.x];
    bf162* d = (bf162*)(g_tvb + (size_t)r * EE + threadIdx.x * 4);
    d[0] = cvt2(val.x, val.y); d[1] = cvt2(val.z, val.w);
    if (threadIdx.x == 0) {
        g_goldtok[r] = tok[b * TTR + t + 1];
        g_maskf[r] = ((t + 1) < lens[b]) ? 1.0f : 0.0f;
    }
}

// ---------------- 128-tile feed-forward GEMM (fp32 out): C = A @ W^T + bias ----------------
__global__ __launch_bounds__(256) void k_ff128(
    const bf16* __restrict__ A, int lda,
    const bf16* __restrict__ W, int ldw,
    const float* __restrict__ bias,
    float* __restrict__ C, int ldc, int K)
{
    extern __shared__ __align__(16) char dyn[];
    float* Cs = (float*)dyn;
    int m0 = blockIdx.x * 128, n0 = blockIdx.y * 128;
    gemm128(A + (size_t)m0 * lda, lda, W + (size_t)n0 * ldw, ldw, K, dyn, Cs, 136);
    int tid = threadIdx.x;
    for (int e = tid; e < 4096; e += 256) {
        int r = e >> 5, c4 = (e & 31) * 4;
        float4 v = *(const float4*)(Cs + r * 136 + c4);
        float4 bv = *(const float4*)(bias + n0 + c4);
        v.x += bv.x; v.y += bv.y; v.z += bv.z; v.w += bv.w;
        *(float4*)(C + (size_t)(m0 + r) * ldc + n0 + c4) = v;
    }
}

// ---------------- 128-tile GEMM (bf16 out, optional bias / bf16 add) ----------------
__global__ __launch_bounds__(256) void k_gemm128_b(
    const bf16* __restrict__ A, int lda,
    const bf16* __restrict__ W, int ldw, int K,
    const float* __restrict__ bias,
    const bf16* __restrict__ addW, int ldadd,
    bf16* __restrict__ out, int ldo)
{
    extern __shared__ __align__(16) char dyn[];
    float* Cs = (float*)dyn;
    int m0 = blockIdx.x * 128, n0 = blockIdx.y * 128;
    gemm128(A + (size_t)m0 * lda, lda, W + (size_t)n0 * ldw, ldw, K, dyn, Cs, 136);
    int tid = threadIdx.x;
    for (int e = tid; e < 4096; e += 256) {
        int r = e >> 5, c4 = (e & 31) * 4;
        float4 v = *(const float4*)(Cs + r * 136 + c4);
        if (bias) {
            float4 bv = *(const float4*)(bias + n0 + c4);
            v.x += bv.x; v.y += bv.y; v.z += bv.z; v.w += bv.w;
        }
        if (addW) {
            const bf16* aw = addW + (size_t)(m0 + r) * ldadd + n0 + c4;
            v.x += __bfloat162float(aw[0]); v.y += __bfloat162float(aw[1]);
            v.z += __bfloat162float(aw[2]); v.w += __bfloat162float(aw[3]);
        }
        bf162* o = (bf162*)(out + (size_t)(m0 + r) * ldo + n0 + c4);
        o[0] = cvt2(v.x, v.y); o[1] = cvt2(v.z, v.w);
    }
}

// ---------------- 128-tile vocab GEMM + fused LSE chunk ----------------
__global__ __launch_bounds__(256) void k_vocab128(const float* __restrict__ bias) {
    extern __shared__ __align__(16) char dyn[];
    float* Cs = (float*)dyn;
    int m0 = blockIdx.x * 128, n0 = blockIdx.y * 128;
    gemm128(g_avallb + (size_t)m0 * DDH, DDH, g_Wout + (size_t)n0 * DDH, DDH, DDH,
            dyn, Cs, 136);
    int tid = threadIdx.x;
    for (int e = tid; e < 4096; e += 256) {
        int r = e >> 5, c4 = (e & 31) * 4;
        float4 v = *(const float4*)(Cs + r * 136 + c4);
        float4 bv = *(const float4*)(bias + n0 + c4);
        v.x += bv.x; v.y += bv.y; v.z += bv.z; v.w += bv.w;
        *(float4*)(Cs + r * 136 + c4) = v;
    }
    __syncthreads();
    int row = tid >> 1, half = tid & 1;
    int rg = m0 + row;
    const float* Cr = Cs + row * 136 + half * 64;
    float m = -1e30f;
#pragma unroll 8
    for (int c = 0; c < 64; c++) m = fmaxf(m, Cr[c]);
    float mo = __shfl_xor_sync(0xffffffffu, m, 1);
    float mn = fmaxf(m, mo);
    float s = 0.f;
#pragma unroll 8
    for (int c = 0; c < 64; c++) s += __expf(Cr[c] - mn);
    s += __shfl_xor_sync(0xffffffffu, s, 1);
    if (rg < MR) {
        if (half == 0) {
            size_t co = ((size_t)rg * NTV + blockIdx.y) * 2;
            g_chunk[co + 0] = mn;
            g_chunk[co + 1] = s;
        }
        int loc = g_goldtok[rg] - n0 - half * 64;
        if (loc >= 0 && loc < 64) g_gold[rg] = Cr[loc];
    }
}

// ---------------- persistent encoder: 64 steps ----------------
__global__ __launch_bounds__(256, 2) void k_enc_persist(
    const bf16* __restrict__ Wf, const bf16* __restrict__ Wr)
{
    extern __shared__ __align__(16) char dyn[];
    float* Cs = (float*)dyn;
    unsigned gen = 0;
    int p = blockIdx.x, tid = threadIdx.x;
    int d = p >> 4;
    int n0 = (p & 15) * 128;
    const bf16* A = g_hsb + d * (BB * HH);
    const bf16* W = (d ? Wr : Wf) + (size_t)n0 * HH;
    const float* pre_base = d ? g_Gr : g_Gf;
    for (int t = 0; t < TSR; t++) {
        gemm_core(A, HH, W, HH, HH, dyn, Cs, 136);
        for (int it = tid; it < 2048; it += 256) {
            int b = it >> 5, jl = it & 31;
            const float* cr = Cs + b * 136 + 4 * jl;
            const float* pre = pre_base + (size_t)(b * TSR + t) * 2048 + n0 + 4 * jl;
            float gi = cr[0] + pre[0];
            float gf = cr[1] + pre[1];
            float gg = cr[2] + pre[2];
            float go = cr[3] + pre[3];
            int j = (n0 >> 2) + jl;
            int si = d * (BB * HH) + (b << 9) + j;
            float c = sigf(gf) * g_cs[si] + sigf(gi) * tanhf(gg);
            float h = sigf(go) * tanhf(c);
            g_cs[si] = c;
            g_hsb[si] = __float2bfloat16(h);
            size_t o = (size_t)(b * TSR + t) * 1024 + d * 512 + j;
            g_Henc[o] = h; g_Cenc[o] = c; g_Hencb[o] = __float2bfloat16(h);
        }
        gsync(0, NBE, gen);
    }
}

// ---------------- persistent decoder: 63 steps, 2 phases/step ----------------
__global__ __launch_bounds__(256, 2) void k_dec_persist(const int* __restrict__ src_lens) {
    extern __shared__ __align__(16) char dyn[];
    float* Cs = (float*)dyn;
    unsigned gen = 0;
    int p = blockIdx.x, tid = threadIdx.x;
    for (int t = 0; t < TD; t++) {
        // ---- Phase A ----
        if (p < 128) {
            int nt = p & 31, ks = p >> 5;
            const bf16* A = g_hb + ks * 256;
            const bf16* W; int ldw;
            if (t == 0) { W = g_WdecR + (size_t)(nt * 128) * 2048 + 1024 + ks * 256; ldw = 2048; }
            else        { W = g_Wgate + (size_t)(nt * 128) * 1024 + ks * 256; ldw = 1024; }
            gemm_core(A, 1024, W, ldw, 256, dyn,
                      g_Pg + (size_t)ks * (64 * 4096) + nt * 128, 4096);
        } else if (t > 0) {
            int q = p - 128, b = q >> 1;
            float* sps = Cs;                         // 64 floats
            if (tid < 64) sps[tid] = g_spg[b * 64 + tid];
            __syncthreads();
            int c0 = (q & 1) * 2048 + tid * 8;
            float acc[8];
#pragma unroll
            for (int i = 0; i < 8; i++) acc[i] = 0.f;
            const bf16* Hc0 = g_HencC + (size_t)(b * 64) * 4096 + c0;
            for (int u = 0; u < 64; u++) {
                float pw = sps[u];
                float4 r0 = *(const float4*)(Hc0 + (size_t)u * 4096);
                const bf162* pp = (const bf162*)&r0;
#pragma unroll
                for (int i = 0; i < 4; i++) {
                    float2 f = __bfloat1622float2(pp[i]);
                    acc[2 * i] += pw * f.x; acc[2 * i + 1] += pw * f.y;
                }
            }
            float* cgw = g_ctxg + (size_t)b * 4096 + c0;
            *(float4*)cgw       = make_float4(acc[0], acc[1], acc[2], acc[3]);
            *(float4*)(cgw + 4) = make_float4(acc[4], acc[5], acc[6], acc[7]);
            __syncthreads();
        }
        gsyncH(NBD, gen);
        // ---- Phase B ----
        if (p < 64) {
            int b = p;
            float* sh = Cs;            // 1024
            float* sc = Cs + 1024;     // 64
            float* sp = Cs + 1088;     // 64
            const float* pre = g_Gdec + (size_t)((t << 6) + b) * 4096;
            const float* P0 = g_Pg + (size_t)b * 4096;
            const float* cg = g_ctxg + (size_t)b * 4096;
#pragma unroll
            for (int u = 0; u < 4; u++) {
                int j = tid + u * 256;
                int col = 4 * j;
                float4 gp = *(const float4*)(pre + col);
                float4 q0 = *(const float4*)(P0 + col);
                float4 q1 = *(const float4*)(P0 + 64 * 4096 + col);
                float4 q2 = *(const float4*)(P0 + 2 * 64 * 4096 + col);
                float4 q3 = *(const float4*)(P0 + 3 * 64 * 4096 + col);
                float gi = gp.x + q0.x + q1.x + q2.x + q3.x;
                float gf = gp.y + q0.y + q1.y + q2.y + q3.y;
                float gg = gp.z + q0.z + q1.z + q2.z + q3.z;
                float go = gp.w + q0.w + q1.w + q2.w + q3.w;
                if (t > 0) {
                    float4 ca = *(const float4*)(g_constA + col);
                    float4 cx = *(const float4*)(cg + col);
                    gi += ca.x + cx.x; gf += ca.y + cx.y;
                    gg += ca.z + cx.z; go += ca.w + cx.w;
                }
                int ci = (b << 10) + j;
                float c = sigf(gf) * g_c[ci] + sigf(gi) * tanhf(gg);
                float h = sigf(go) * tanhf(c);
                g_c[ci] = c;
                sh[j] = h;
                bf16 hb = __float2bfloat16(h);
                g_hb[ci] = hb;
                g_yall[(size_t)((t << 6) + b) * 2048 + j] = hb;
            }
            __syncthreads();
            // attention scores
            {
                int tt = tid >> 2, q = tid & 3;
                const bf162* He = (const bf162*)(g_Hencb + (size_t)(b * TSR + tt) * 1024 + q * 256);
                const float* hh = sh + q * 256;
                float s = 0.f;
#pragma unroll 8
                for (int j = 0; j < 128; j++) {
                    bf162 v = He[j];
                    s += hh[2 * j] * __bfloat162float(v.x) + hh[2 * j + 1] * __bfloat162float(v.y);
                }
                s += __shfl_xor_sync(0xffffffffu, s, 1);
                s += __shfl_xor_sync(0xffffffffu, s, 2);
                if (q == 0) sc[tt] = s;
            }
            __syncthreads();
            int L = src_lens[b];
            float m = -1e30f;
            for (int u = 0; u < 64; u++) if (u < L) m = fmaxf(m, sc[u]);
            float den = 0.f;
            for (int u = 0; u < 64; u++) if (u < L) den += __expf(sc[u] - m);
            if (tid < 64) {
                float pv = (tid < L) ? (__expf(sc[tid] - m) / den) : 0.f;
                sp[tid] = pv;
                g_spg[b * 64 + tid] = pv;
            }
            __syncthreads();
            // ctx (1024) -> yall[..., 1024:2048]
            {
                int j0 = tid * 4;
                float a0 = 0.f, a1 = 0.f, a2 = 0.f, a3 = 0.f;
                for (int u = 0; u < L; u++) {
                    float pw = sp[u];
                    const bf162* Hr = (const bf162*)(g_Hencb + (size_t)(b * TSR + u) * 1024 + j0);
                    bf162 v0 = Hr[0], v1 = Hr[1];
                    a0 += pw * __bfloat162float(v0.x); a1 += pw * __bfloat162float(v0.y);
                    a2 += pw * __bfloat162float(v1.x); a3 += pw * __bfloat162float(v1.y);
                }
                bf162* co = (bf162*)(g_yall + (size_t)((t << 6) + b) * 2048 + 1024 + j0);
                co[0] = cvt2(a0, a1); co[1] = cvt2(a2, a3);
            }
        }
        gsyncH(NBD, gen);
    }
}

// ---------------- decoder init (fp32 path, one-time) ----------------
__global__ void k_final(const int* __restrict__ src_lens) {
    int i = blockIdx.x * blockDim.x + threadIdx.x;    // < 64*2048
    int b = i >> 11, j = i & 2047;
    int last = src_lens[b] - 1;
    size_t o = (size_t)(b * TSR + last) * 1024;
    g_final[i] = (j < 1024) ? g_Henc[o + j] : g_Cenc[o + j - 1024];
}

__global__ void k_sgemm_init(const float* __restrict__ W) {
    __shared__ float As[16][64];
    __shared__ float Ws[16][32];
    int z = blockIdx.z;
    int koff = z * 512;
    int tid = threadIdx.x;
    int n0 = blockIdx.x * 32;
    int ty = tid >> 3, tx = tid & 7;
    int lr = tid >> 1, lc = (tid & 1) * 8;
    int wr = tid >> 2, wc = (tid & 3) * 4;
    float acc[4][4];
#pragma unroll
    for (int i = 0; i < 4; i++)
#pragma unroll
        for (int j = 0; j < 4; j++) acc[i][j] = 0.f;
    const float* Ab = g_final + (size_t)lr * 2048 + koff + lc;
    const float* Wb = W + (size_t)(n0 + wr) * 2048 + koff + wc;
    for (int k0 = 0; k0 < 512; k0 += 16) {
        float4 a0 = *(const float4*)(Ab + k0);
        float4 a1 = *(const float4*)(Ab + k0 + 4);
        float4 b0 = *(const float4*)(Wb + k0);
        __syncthreads();
        As[lc + 0][lr] = a0.x; As[lc + 1][lr] = a0.y; As[lc + 2][lr] = a0.z; As[lc + 3][lr] = a0.w;
        As[lc + 4][lr] = a1.x; As[lc + 5][lr] = a1.y; As[lc + 6][lr] = a1.z; As[lc + 7][lr] = a1.w;
        Ws[wc + 0][wr] = b0.x; Ws[wc + 1][wr] = b0.y; Ws[wc + 2][wr] = b0.z; Ws[wc + 3][wr] = b0.w;
        __syncthreads();
#pragma unroll
        for (int kk = 0; kk < 16; kk++) {
            float a[4], b[4];
#pragma unroll
            for (int i = 0; i < 4; i++) a[i] = As[kk][ty * 4 + i];
#pragma unroll
            for (int j = 0; j < 4; j++) b[j] = Ws[kk][tx * 4 + j];
#pragma unroll
            for (int i = 0; i < 4; i++)
#pragma unroll
                for (int j = 0; j < 4; j++) acc[i][j] += a[i] * b[j];
        }
    }
    float* Pz = g_Phid + (size_t)z * (BB * DDH);
#pragma unroll
    for (int i = 0; i < 4; i++)
#pragma unroll
        for (int j = 0; j < 4; j++)
            Pz[(ty * 4 + i) * DDH + n0 + tx * 4 + j] = acc[i][j];
}

__global__ void k_init(const float* __restrict__ init_b) {
    int i = blockIdx.x * blockDim.x + threadIdx.x;    // < 64*1024
    int j = i & 1023;
    float c = init_b[j];
#pragma unroll
    for (int s = 0; s < 4; s++) c += g_Phid[s * (BB * DDH) + i];
    g_c[i] = c;
    g_hb[i] = __float2bfloat16(tanhf(c));
}

// ---------------- per-row LSE combine + masked sum ----------------
__global__ void k_rowlse() {
    int tid = threadIdx.x;                 // 256
    int b = tid >> 2, q = tid & 3;
    int row = blockIdx.x * 64 + b;
    const float* ch = g_chunk + (size_t)row * NTV * 2;
    float m = -1e30f;
    for (int i = q; i < NTV; i += 4) m = fmaxf(m, ch[2 * i]);
    m = fmaxf(m, __shfl_xor_sync(0xffffffffu, m, 1));
    m = fmaxf(m, __shfl_xor_sync(0xffffffffu, m, 2));
    float s = 0.f;
    for (int i = q; i < NTV; i += 4) s += ch[2 * i + 1] * __expf(ch[2 * i] - m);
    s += __shfl_xor_sync(0xffffffffu, s, 1);
    s += __shfl_xor_sync(0xffffffffu, s, 2);
    if (q == 0) {
        float lse = m + logf(s);
        g_rowval[row] = (g_gold[row] - lse) * g_maskf[row];
    }
}

__global__ void k_sum(float* __restrict__ out) {
    __shared__ float sm[256];
    int tid = threadIdx.x;
    float s = 0.f;
    for (int i = tid; i < MR; i += 256) s += g_rowval[i];
    sm[tid] = s;
    __syncthreads();
    for (int st = 128; st > 0; st >>= 1) {
        if (tid < st) sm[tid] += sm[tid + st];
        __syncthreads();
    }
    if (tid == 0) out[0] = sm[0];
}

// ---------------- launch ----------------
extern "C" void kernel_launch(void* const* d_in, const int* in_sizes, int n_in,
                              void* d_out, int out_size) {
    (void)in_sizes; (void)n_in; (void)out_size;
    const int*   src_tokens = (const int*)d_in[0];
    const int*   src_lens   = (const int*)d_in[1];
    const int*   trg_tokens = (const int*)d_in[2];
    const int*   trg_lens   = (const int*)d_in[3];
    const float* src_emb    = (const float*)d_in[4];
    const float* trg_emb    = (const float*)d_in[5];
    const float* enc_Wih    = (const float*)d_in[6];
    const float* enc_Whh    = (const float*)d_in[7];
    const float* enc_b      = (const float*)d_in[8];
    const float* rev_Wih    = (const float*)d_in[9];
    const float* rev_Whh    = (const float*)d_in[10];
    const float* rev_b      = (const float*)d_in[11];
    const float* dec_Wih    = (const float*)d_in[12];
    const float* dec_Whh    = (const float*)d_in[13];
    const float* dec_b      = (const float*)d_in[14];
    const float* hid_W      = (const float*)d_in[15];
    const float* hid_b      = (const float*)d_in[16];
    const float* out_W      = (const float*)d_in[17];
    const float* out_b      = (const float*)d_in[18];
    const float* init_W     = (const float*)d_in[19];
    const float* init_b     = (const float*)d_in[20];

    bf16 *p_svb, *p_tvb, *p_Wencf, *p_Wencr, *p_Whhf, *p_Whhr, *p_WdecE, *p_WhidB,
         *p_Wout, *p_WhidLT, *p_WhidRT, *p_Wgate, *p_WcombC, *p_HencC, *p_Hencb,
         *p_WdecR, *p_yall, *p_avallb;
    float *p_Gf, *p_Gr, *p_Gdec, *p_bencf, *p_bencr, *p_bdec;
    cudaGetSymbolAddress((void**)&p_svb, g_svb);
    cudaGetSymbolAddress((void**)&p_tvb, g_tvb);
    cudaGetSymbolAddress((void**)&p_Wencf, g_WencfP);
    cudaGetSymbolAddress((void**)&p_Wencr, g_WencrP);
    cudaGetSymbolAddress((void**)&p_Whhf, g_WhhfP);
    cudaGetSymbolAddress((void**)&p_Whhr, g_WhhrP);
    cudaGetSymbolAddress((void**)&p_WdecE, g_WdecE);
    cudaGetSymbolAddress((void**)&p_WhidB, g_WhidB);
    cudaGetSymbolAddress((void**)&p_Wout, g_Wout);
    cudaGetSymbolAddress((void**)&p_WhidLT, g_WhidLT);
    cudaGetSymbolAddress((void**)&p_WhidRT, g_WhidRT);
    cudaGetSymbolAddress((void**)&p_Wgate, g_Wgate);
    cudaGetSymbolAddress((void**)&p_WcombC, g_WcombC);
    cudaGetSymbolAddress((void**)&p_HencC, g_HencC);
    cudaGetSymbolAddress((void**)&p_Hencb, g_Hencb);
    cudaGetSymbolAddress((void**)&p_WdecR, g_WdecR);
    cudaGetSymbolAddress((void**)&p_yall, g_yall);
    cudaGetSymbolAddress((void**)&p_avallb, g_avallb);
    cudaGetSymbolAddress((void**)&p_Gf, g_Gf);
    cudaGetSymbolAddress((void**)&p_Gr, g_Gr);
    cudaGetSymbolAddress((void**)&p_Gdec, g_Gdec);
    cudaGetSymbolAddress((void**)&p_bencf, g_bencfP);
    cudaGetSymbolAddress((void**)&p_bencr, g_bencrP);
    cudaGetSymbolAddress((void**)&p_bdec, g_bdecP);

    // dynamic smem opt-in
    cudaFuncSetAttribute(k_ff128, cudaFuncAttributeMaxDynamicSharedMemorySize, DYN2);
    cudaFuncSetAttribute(k_gemm128_b, cudaFuncAttributeMaxDynamicSharedMemorySize, DYN2);
    cudaFuncSetAttribute(k_vocab128, cudaFuncAttributeMaxDynamicSharedMemorySize, DYN2);
    cudaFuncSetAttribute(k_enc_persist, cudaFuncAttributeMaxDynamicSharedMemorySize, DYN_SMEM);
    cudaFuncSetAttribute(k_dec_persist, cudaFuncAttributeMaxDynamicSharedMemorySize, DYN_SMEM);

    k_zero_state<<<256, 256>>>();
    k_zeropad<<<512, 256>>>();
    k_gather_src<<<BB * TSR, 128>>>(src_tokens, src_emb);
    k_gather_trg<<<MR, 128>>>(trg_tokens, trg_lens, trg_emb);

    // weight conversions + gate-interleave permutations
    k_permW512<<<2048, 128>>>(enc_Wih, p_Wencf, 512, 512);
    k_permW512<<<2048, 128>>>(rev_Wih, p_Wencr, 512, 512);
    k_permW512<<<2048, 128>>>(enc_Whh, p_Whhf, 512, 512);
    k_permW512<<<2048, 128>>>(rev_Whh, p_Whhr, 512, 512);
    k_permW512<<<4096, 128>>>(dec_Wih, p_WdecE, 1024, 1536);
    k_permDecR<<<4096, 256>>>(dec_Wih, dec_Whh);
    k_permB<<<8, 256>>>(enc_b, p_bencf, 512);
    k_permB<<<8, 256>>>(rev_b, p_bencr, 512);
    k_permB<<<16, 256>>>(dec_b, p_bdec, 1024);
    k_f2b<<<(DDH * 2048 / 4 + 255) / 256, 256>>>(hid_W, p_WhidB, DDH * 2048 / 4);
    k_f2b<<<(VOC * DDH / 4 + 255) / 256, 256>>>(out_W, p_Wout, VOC * DDH / 4);
    k_transpose_hid<<<dim3(32, 32, 2), dim3(32, 8)>>>(hid_W);
    k_const<<<512, 256>>>(hid_b);

    // composed decoder weights: Wgate = WA@WhidL + Whh ; WcombC = WA@WhidR
    k_gemm128_b<<<dim3(32, 8), 256, DYN2>>>(p_WdecR, 2048, p_WhidLT, 1024, 1024,
                                            (const float*)0, p_WdecR + 1024, 2048,
                                            p_Wgate, 1024);
    k_gemm128_b<<<dim3(32, 8), 256, DYN2>>>(p_WdecR, 2048, p_WhidRT, 1024, 1024,
                                            (const float*)0, (const bf16*)0, 0,
                                            p_WcombC, 1024);

    // input projections (tensor cores, interleaved outputs)
    k_ff128<<<dim3(32, 16), 256, DYN2>>>(p_svb, EE, p_Wencf, EE, p_bencf, p_Gf, 2048, EE);
    k_ff128<<<dim3(32, 16), 256, DYN2>>>(p_svb, EE, p_Wencr, EE, p_bencr, p_Gr, 2048, EE);
    k_ff128<<<dim3(32, 32), 256, DYN2>>>(p_tvb, EE, p_WdecE, EE, p_bdec, p_Gdec, 4096, EE);

    // encoder recurrence (persistent)
    k_enc_persist<<<NBE, 256, DYN_SMEM>>>(p_Whhf, p_Whhr);

    // HencC = Henc @ WcombC^T  (needs encoder output)
    k_gemm128_b<<<dim3(32, 32), 256, DYN2>>>(p_Hencb, 1024, p_WcombC, 1024, 1024,
                                             (const float*)0, (const bf16*)0, 0,
                                             p_HencC, 4096);

    // decoder init state
    k_final<<<512, 256>>>(src_lens);
    k_sgemm_init<<<dim3(32, 1, 4), 128>>>(init_W);
    k_init<<<256, 256>>>(init_b);

    // decoder recurrence (persistent, 2 phases/step, hierarchical barrier)
    k_dec_persist<<<NBD, 256, DYN_SMEM>>>(src_lens);

    // deferred hid GEMM: avall = [h|ctx] @ hid_W^T + hid_b
    k_gemm128_b<<<dim3(32, 8), 256, DYN2>>>(p_yall, 2048, p_WhidB, 2048, 2048,
                                            hid_b, (const bf16*)0, 0, p_avallb, 1024);

    // vocab projection + LSE (128-tile)
    k_vocab128<<<dim3(32, NTV), 256, DYN2>>>(out_b);
    k_rowlse<<<63, 256>>>();
    k_sum<<<1, 256>>>((float*)d_out);
}

// round 15
// speedup vs baseline: 1.0751x; 1.0496x over previous
#include <cuda_runtime.h>
#include <cuda_bf16.h>
#include <mma.h>
#include <math.h>
#include <stdint.h>
using namespace nvcuda;

// ---------------- problem constants ----------------
#define BB   64      // batch
#define TSR  64      // src len
#define TTR  64      // trg len
#define EE   512     // embedding
#define HH   512     // encoder hidden per dir
#define DDH  1024    // decoder hidden
#define VOC  32000
#define TD   63              // decode steps
#define MR   (TD*BB)         // 4032 rows
#define MRP  4096            // padded row count for 128-tiles
#define NTV  (VOC/128)       // 250 column tiles of vocab
#define NBE  32              // encoder recurrence blocks
#define NBENC 148            // total encoder-kernel grid (32 recurrence + 116 workers)
#define NBD  256             // decoder persistent grid

#define AS_STAGE (64*72)
#define WS_STAGE (128*72)
#define DYN_SMEM ((2*AS_STAGE + 2*WS_STAGE) * 2)   // 55296 bytes (64x128 core)

#define G128_STAGE (128*72)                         // bf16 elems per tensor per stage
#define DYN2 (4*G128_STAGE*2)                       // 73728 bytes (128x128 core)

typedef __nv_bfloat16 bf16;
typedef __nv_bfloat162 bf162;

// ---------------- static device scratch ----------------
__device__ bf16 g_svb  [BB*TSR*EE];       // src embedded bf16, row = b*TSR+t
__device__ bf16 g_tvb  [MRP*EE];          // trg embedded bf16, row = t*BB+b (padded)
__device__ bf16 g_WencfP[4*HH*EE];        // enc_Wih bf16, gate-interleaved rows
__device__ bf16 g_WencrP[4*HH*EE];
__device__ bf16 g_WhhfP [4*HH*HH];        // enc_Whh bf16 interleaved
__device__ bf16 g_WhhrP [4*HH*HH];
__device__ bf16 g_WdecE [4*DDH*EE];       // dec_Wih[:, :512] interleaved
__device__ bf16 g_WdecR [4*DDH*2048];     // [dec_Wih[:,512:1536] | dec_Whh] interleaved
__device__ bf16 g_WhidB [DDH*2*DDH];      // hid_W bf16 plain [1024][2048]
__device__ bf16 g_WhidLT[DDH*DDH];        // hid_W left half transposed  [k][j]
__device__ bf16 g_WhidRT[DDH*DDH];        // hid_W right half transposed [k][j]
__device__ bf16 g_Wgate [4*DDH*DDH];      // WA@WhidL + Whh (interleaved rows)
__device__ bf16 g_WcombC[4*DDH*DDH];      // WA@WhidR (interleaved rows)
__device__ bf16 g_HencC [BB*TSR*4*DDH];   // Henc @ WcombC^T  [(b*64+u)][4096]
__device__ bf16 g_Wout  [VOC*DDH];        // out_W bf16 plain
__device__ bf16 g_avallb[MRP*DDH];        // all av rows bf16 (padded)
__device__ bf16 g_yall  [MRP*2048];       // [h|ctx] rows (padded)

__device__ float g_bencfP[4*HH];          // permuted biases (fp32)
__device__ float g_bencrP[4*HH];
__device__ float g_bdecP [4*DDH];
__device__ float g_constA[4*DDH];         // WA_P @ hid_b

__device__ float g_Gf   [BB*TSR*4*HH];    // enc fwd preact (interleaved cols)
__device__ float g_Gr   [BB*TSR*4*HH];
__device__ float g_Gdec [MRP*4*DDH];      // dec preact (emb part + bias, interleaved)
__device__ float g_Henc [BB*TSR*2*HH];    // fp32 (for final-state gather)
__device__ float g_Cenc [BB*TSR*2*HH];
__device__ bf16  g_Hencb[BB*TSR*2*HH];    // bf16 copy for attention / HencC GEMM
__device__ bf16  g_hsb  [2*BB*HH];        // enc running h bf16 (both dirs)
__device__ float g_cs   [2*BB*HH];        // enc running c fp32
__device__ float g_c    [BB*DDH];         // dec c fp32
__device__ bf16  g_hb   [BB*DDH];         // dec h bf16 (gates GEMM input)
__device__ float g_ctxg [BB*4*DDH];       // ctx-contribution to next gates (fp32)
__device__ float g_spg  [BB*64];          // softmax probs (global, for ctxg blocks)
__device__ float g_Pg   [4*BB*4*DDH];     // gates split-K partials (4 x [64,4096])
__device__ float g_Phid [4*BB*DDH];       // init-GEMM split-K partials
__device__ float g_final[BB*2*DDH];       // concat(Henc,Cenc) at last
__device__ float g_chunk[MR*NTV*2];       // per-tile (max, sumexp)
__device__ float g_gold [MR];
__device__ int   g_goldtok[MR];
__device__ float g_maskf[MR];
__device__ float g_rowval[MR];
__device__ unsigned g_bar[8];             // [0]=cntE [1]=genE [4]=cntD [5]=genD

__device__ __forceinline__ float sigf(float x) { return 1.0f / (1.0f + expf(-x)); }
__device__ __forceinline__ bf162 cvt2(float a, float b) {
    return __float22bfloat162_rn(make_float2(a, b));
}

// ---------------- device-wide software barrier ----------------
__device__ __forceinline__ void gsync(int base, unsigned nb, unsigned& mygen) {
    __threadfence();
    __syncthreads();
    if (threadIdx.x == 0) {
        unsigned g = mygen;
        if (atomicAdd(&g_bar[base], 1u) == nb - 1u) {
            atomicExch(&g_bar[base], 0u);
            __threadfence();
            atomicExch(&g_bar[base + 1], g + 1u);
        } else {
            volatile unsigned* vg = (volatile unsigned*)&g_bar[base + 1];
            while (*vg == g) __nanosleep(64);
        }
    }
    mygen++;
    __syncthreads();
}

// ============ 64x128 GEMM core (persistent kernels), K-tile 64 ============
__device__ __forceinline__ void gemm_core(
    const bf16* __restrict__ A, int lda,
    const bf16* __restrict__ W, int ldw,
    int K, char* smem, float* out, int ldo)
{
    bf16* As = (bf16*)smem;                  // 2 stages x 64 x 72
    bf16* Ws = (bf16*)smem + 2 * AS_STAGE;   // 2 stages x 128 x 72
    int tid = threadIdx.x;
    int wid = tid >> 5;
    int wr = (wid & 1) * 32, wc = (wid >> 1) * 32;

    wmma::fragment<wmma::accumulator, 16, 16, 16, float> acc[2][2];
#pragma unroll
    for (int i = 0; i < 2; i++)
#pragma unroll
        for (int j = 0; j < 2; j++) wmma::fill_fragment(acc[i][j], 0.f);

    int ar = tid >> 2, ac = (tid & 3) * 16;
    int wq = tid >> 1, wz = (tid & 1) * 32;
    const bf16* Ap = A + (size_t)ar * lda + ac;
    const bf16* Wp = W + (size_t)wq * ldw + wz;

    float4 a0 = *(const float4*)Ap;
    float4 a1 = *(const float4*)(Ap + 8);
    float4 w0 = *(const float4*)Wp;
    float4 w1 = *(const float4*)(Wp + 8);
    float4 w2 = *(const float4*)(Wp + 16);
    float4 w3 = *(const float4*)(Wp + 24);
    *(float4*)&As[ar * 72 + ac]     = a0;
    *(float4*)&As[ar * 72 + ac + 8] = a1;
    *(float4*)&Ws[wq * 72 + wz]      = w0;
    *(float4*)&Ws[wq * 72 + wz + 8]  = w1;
    *(float4*)&Ws[wq * 72 + wz + 16] = w2;
    *(float4*)&Ws[wq * 72 + wz + 24] = w3;

    int niter = K >> 6;
    int cur = 0;
    for (int it = 0; it < niter; ++it) {
        __syncthreads();
        if (it + 1 < niter) {
            const bf16* Apn = Ap + (it + 1) * 64;
            const bf16* Wpn = Wp + (it + 1) * 64;
            a0 = *(const float4*)Apn;
            a1 = *(const float4*)(Apn + 8);
            w0 = *(const float4*)Wpn;
            w1 = *(const float4*)(Wpn + 8);
            w2 = *(const float4*)(Wpn + 16);
            w3 = *(const float4*)(Wpn + 24);
        }
        const bf16* Ab = As + cur * AS_STAGE;
        const bf16* Wb = Ws + cur * WS_STAGE;
#pragma unroll
        for (int kk = 0; kk < 64; kk += 16) {
            wmma::fragment<wmma::matrix_a, 16, 16, 16, bf16, wmma::row_major> af[2];
            wmma::fragment<wmma::matrix_b, 16, 16, 16, bf16, wmma::col_major> bfr[2];
            wmma::load_matrix_sync(af[0], Ab + wr * 72 + kk, 72);
            wmma::load_matrix_sync(af[1], Ab + (wr + 16) * 72 + kk, 72);
            wmma::load_matrix_sync(bfr[0], Wb + wc * 72 + kk, 72);
            wmma::load_matrix_sync(bfr[1], Wb + (wc + 16) * 72 + kk, 72);
#pragma unroll
            for (int i = 0; i < 2; i++)
#pragma unroll
                for (int j = 0; j < 2; j++)
                    wmma::mma_sync(acc[i][j], af[i], bfr[j], acc[i][j]);
        }
        if (it + 1 < niter) {
            int nb = cur ^ 1;
            *(float4*)&As[nb * AS_STAGE + ar * 72 + ac]     = a0;
            *(float4*)&As[nb * AS_STAGE + ar * 72 + ac + 8] = a1;
            *(float4*)&Ws[nb * WS_STAGE + wq * 72 + wz]      = w0;
            *(float4*)&Ws[nb * WS_STAGE + wq * 72 + wz + 8]  = w1;
            *(float4*)&Ws[nb * WS_STAGE + wq * 72 + wz + 16] = w2;
            *(float4*)&Ws[nb * WS_STAGE + wq * 72 + wz + 24] = w3;
        }
        cur ^= 1;
    }
    __syncthreads();
#pragma unroll
    for (int i = 0; i < 2; i++)
#pragma unroll
        for (int j = 0; j < 2; j++)
            wmma::store_matrix_sync(out + (size_t)(wr + i * 16) * ldo + wc + j * 16,
                                    acc[i][j], ldo, wmma::mem_row_major);
    __syncthreads();
}

// ============ 128x128 GEMM core (feed-forward), warp tile 32x64 ============
__device__ __forceinline__ void gemm128(
    const bf16* __restrict__ A, int lda,
    const bf16* __restrict__ W, int ldw,
    int K, char* smem, float* out, int ldo)
{
    bf16* As = (bf16*)smem;                     // 2 stages x 128 x 72
    bf16* Ws = (bf16*)smem + 2 * G128_STAGE;    // 2 stages x 128 x 72
    int tid = threadIdx.x;
    int wid = tid >> 5;
    int wm = (wid & 3) * 32, wn = (wid >> 2) * 64;

    wmma::fragment<wmma::accumulator, 16, 16, 16, float> acc[2][4];
#pragma unroll
    for (int i = 0; i < 2; i++)
#pragma unroll
        for (int j = 0; j < 4; j++) wmma::fill_fragment(acc[i][j], 0.f);

    int r = tid >> 1, hc = (tid & 1) * 32;
    const bf16* Ap = A + (size_t)r * lda + hc;
    const bf16* Wp = W + (size_t)r * ldw + hc;

    float4 a0 = *(const float4*)Ap;
    float4 a1 = *(const float4*)(Ap + 8);
    float4 a2 = *(const float4*)(Ap + 16);
    float4 a3 = *(const float4*)(Ap + 24);
    float4 w0 = *(const float4*)Wp;
    float4 w1 = *(const float4*)(Wp + 8);
    float4 w2 = *(const float4*)(Wp + 16);
    float4 w3 = *(const float4*)(Wp + 24);
    {
        uint32_t o = (uint32_t)r * 72u + (uint32_t)hc;
        *(float4*)&As[o] = a0; *(float4*)&As[o + 8] = a1;
        *(float4*)&As[o + 16] = a2; *(float4*)&As[o + 24] = a3;
        *(float4*)&Ws[o] = w0; *(float4*)&Ws[o + 8] = w1;
        *(float4*)&Ws[o + 16] = w2; *(float4*)&Ws[o + 24] = w3;
    }

    int niter = K >> 6;
    int cur = 0;
    for (int it = 0; it < niter; ++it) {
        __syncthreads();
        if (it + 1 < niter) {
            const bf16* Apn = Ap + (it + 1) * 64;
            const bf16* Wpn = Wp + (it + 1) * 64;
            a0 = *(const float4*)Apn;       a1 = *(const float4*)(Apn + 8);
            a2 = *(const float4*)(Apn + 16); a3 = *(const float4*)(Apn + 24);
            w0 = *(const float4*)Wpn;       w1 = *(const float4*)(Wpn + 8);
            w2 = *(const float4*)(Wpn + 16); w3 = *(const float4*)(Wpn + 24);
        }
        const bf16* Ab = As + cur * G128_STAGE;
        const bf16* Wb = Ws + cur * G128_STAGE;
#pragma unroll
        for (int kk = 0; kk < 64; kk += 16) {
            wmma::fragment<wmma::matrix_a, 16, 16, 16, bf16, wmma::row_major> af[2];
            wmma::fragment<wmma::matrix_b, 16, 16, 16, bf16, wmma::col_major> bfr[4];
            wmma::load_matrix_sync(af[0], Ab + wm * 72 + kk, 72);
            wmma::load_matrix_sync(af[1], Ab + (wm + 16) * 72 + kk, 72);
#pragma unroll
            for (int j = 0; j < 4; j++)
                wmma::load_matrix_sync(bfr[j], Wb + (wn + j * 16) * 72 + kk, 72);
#pragma unroll
            for (int i = 0; i < 2; i++)
#pragma unroll
                for (int j = 0; j < 4; j++)
                    wmma::mma_sync(acc[i][j], af[i], bfr[j], acc[i][j]);
        }
        if (it + 1 < niter) {
            int nb = cur ^ 1;
            uint32_t o = (uint32_t)nb * G128_STAGE + (uint32_t)r * 72u + (uint32_t)hc;
            *(float4*)&As[o] = a0; *(float4*)&As[o + 8] = a1;
            *(float4*)&As[o + 16] = a2; *(float4*)&As[o + 24] = a3;
            *(float4*)&Ws[o] = w0; *(float4*)&Ws[o + 8] = w1;
            *(float4*)&Ws[o + 16] = w2; *(float4*)&Ws[o + 24] = w3;
        }
        cur ^= 1;
    }
    __syncthreads();
#pragma unroll
    for (int i = 0; i < 2; i++)
#pragma unroll
        for (int j = 0; j < 4; j++)
            wmma::store_matrix_sync(out + (size_t)(wm + i * 16) * ldo + wn + j * 16,
                                    acc[i][j], ldo, wmma::mem_row_major);
    __syncthreads();
}

// ---------------- conversions / permutations ----------------
__global__ void k_f2b(const float* __restrict__ x, bf16* __restrict__ y, int n4) {
    int i = blockIdx.x * blockDim.x + threadIdx.x;
    if (i < n4) {
        float4 v = ((const float4*)x)[i];
        ((bf162*)y)[2 * i]     = cvt2(v.x, v.y);
        ((bf162*)y)[2 * i + 1] = cvt2(v.z, v.w);
    }
}

__global__ void k_permW512(const float* __restrict__ W, bf16* __restrict__ out,
                           int J, int ldin) {
    int row = blockIdx.x;
    int j = row >> 2, g = row & 3;
    const float4* src = (const float4*)(W + (size_t)(g * J + j) * ldin);
    bf162* dst = (bf162*)(out + (size_t)row * 512);
    int t = threadIdx.x;                   // 128
    float4 v = src[t];
    dst[2 * t]     = cvt2(v.x, v.y);
    dst[2 * t + 1] = cvt2(v.z, v.w);
}

__global__ void k_permDecR(const float* __restrict__ Wih, const float* __restrict__ Whh) {
    int row = blockIdx.x;                  // 4096
    int j = row >> 2, g = row & 3;
    int t = threadIdx.x;                   // 256, 8 elems each
    const float* src = (t < 128)
        ? (Wih + (size_t)(g * 1024 + j) * 1536 + 512 + t * 8)
        : (Whh + (size_t)(g * 1024 + j) * 1024 + (t - 128) * 8);
    bf162* dst = (bf162*)(g_WdecR + (size_t)row * 2048 + t * 8);
    float4 a = *(const float4*)src;
    float4 b = *(const float4*)(src + 4);
    dst[0] = cvt2(a.x, a.y); dst[1] = cvt2(a.z, a.w);
    dst[2] = cvt2(b.x, b.y); dst[3] = cvt2(b.z, b.w);
}

__global__ void k_permB(const float* __restrict__ b, float* __restrict__ out, int J) {
    int i = blockIdx.x * blockDim.x + threadIdx.x;
    if (i < 4 * J) { int j = i >> 2, g = i & 3; out[i] = b[g * J + j]; }
}

// transpose hid_W halves -> bf16 [k][j]
__global__ void k_transpose_hid(const float* __restrict__ W) {
    __shared__ float tile[32][33];
    int half = blockIdx.z;
    int k0 = blockIdx.x * 32;
    int j0 = blockIdx.y * 32;
    int tx = threadIdx.x, ty = threadIdx.y;   // 32 x 8
#pragma unroll
    for (int i = 0; i < 32; i += 8)
        tile[ty + i][tx] = W[(size_t)(j0 + ty + i) * 2048 + half * 1024 + k0 + tx];
    __syncthreads();
    bf16* out = half ? g_WhidRT : g_WhidLT;
#pragma unroll
    for (int i = 0; i < 32; i += 8)
        out[(size_t)(k0 + ty + i) * 1024 + j0 + tx] = __float2bfloat16(tile[tx][ty + i]);
}

// constA[row] = dot(WA_P[row,:], hid_b)
__global__ void k_const(const float* __restrict__ hid_b) {
    int row = blockIdx.x * 8 + (threadIdx.x >> 5);
    int lane = threadIdx.x & 31;
    const bf16* wr = g_WdecR + (size_t)row * 2048;
    float s = 0.f;
    for (int k = lane; k < 1024; k += 32) s += __bfloat162float(wr[k]) * hid_b[k];
#pragma unroll
    for (int o = 16; o > 0; o >>= 1) s += __shfl_xor_sync(0xffffffffu, s, o);
    if (lane == 0) g_constA[row] = s;
}

// ---------------- init / gathers ----------------
__global__ void k_zero_state() {
    int i = blockIdx.x * blockDim.x + threadIdx.x;
    if (i < 2 * BB * HH) { g_cs[i] = 0.f; g_hsb[i] = __float2bfloat16(0.f); }
    if (i < 8) g_bar[i] = 0u;
}

// zero the pad rows (rows MR..MRP) of avall / tvb / yall
__global__ void k_zeropad() {
    int i = blockIdx.x * blockDim.x + threadIdx.x;
    bf16 z = __float2bfloat16(0.f);
    if (i < 64 * 1024) g_avallb[MR * DDH + i] = z;
    if (i < 64 * 512)  g_tvb[MR * EE + i] = z;
    if (i < 64 * 2048) g_yall[(size_t)MR * 2048 + i] = z;
}

__global__ void k_gather_src(const int* __restrict__ tok, const float* __restrict__ emb) {
    int r = blockIdx.x;
    int v = tok[r];
    float4 val = ((const float4*)(emb + (size_t)v * EE))[threadIdx.x];
    bf162* d = (bf162*)(g_svb + (size_t)r * EE + threadIdx.x * 4);
    d[0] = cvt2(val.x, val.y); d[1] = cvt2(val.z, val.w);
}

__global__ void k_gather_trg(const int* __restrict__ tok, const int* __restrict__ lens,
                             const float* __restrict__ emb) {
    int r = blockIdx.x;                    // t*BB + b
    int t = r >> 6, b = r & 63;
    int v = tok[b * TTR + t];
    float4 val = ((const float4*)(emb + (size_t)v * EE))[threadIdx.x];
    bf162* d = (bf162*)(g_tvb + (size_t)r * EE + threadIdx.x * 4);
    d[0] = cvt2(val.x, val.y); d[1] = cvt2(val.z, val.w);
    if (threadIdx.x == 0) {
        g_goldtok[r] = tok[b * TTR + t + 1];
        g_maskf[r] = ((t + 1) < lens[b]) ? 1.0f : 0.0f;
    }
}

// ---------------- 128-tile feed-forward GEMM (fp32 out): C = A @ W^T + bias ----------------
__global__ __launch_bounds__(256) void k_ff128(
    const bf16* __restrict__ A, int lda,
    const bf16* __restrict__ W, int ldw,
    const float* __restrict__ bias,
    float* __restrict__ C, int ldc, int K)
{
    extern __shared__ __align__(16) char dyn[];
    float* Cs = (float*)dyn;
    int m0 = blockIdx.x * 128, n0 = blockIdx.y * 128;
    gemm128(A + (size_t)m0 * lda, lda, W + (size_t)n0 * ldw, ldw, K, dyn, Cs, 136);
    int tid = threadIdx.x;
    for (int e = tid; e < 4096; e += 256) {
        int r = e >> 5, c4 = (e & 31) * 4;
        float4 v = *(const float4*)(Cs + r * 136 + c4);
        float4 bv = *(const float4*)(bias + n0 + c4);
        v.x += bv.x; v.y += bv.y; v.z += bv.z; v.w += bv.w;
        *(float4*)(C + (size_t)(m0 + r) * ldc + n0 + c4) = v;
    }
}

// ---------------- 128-tile GEMM (bf16 out, optional bias / bf16 add) ----------------
__global__ __launch_bounds__(256) void k_gemm128_b(
    const bf16* __restrict__ A, int lda,
    const bf16* __restrict__ W, int ldw, int K,
    const float* __restrict__ bias,
    const bf16* __restrict__ addW, int ldadd,
    bf16* __restrict__ out, int ldo)
{
    extern __shared__ __align__(16) char dyn[];
    float* Cs = (float*)dyn;
    int m0 = blockIdx.x * 128, n0 = blockIdx.y * 128;
    gemm128(A + (size_t)m0 * lda, lda, W + (size_t)n0 * ldw, ldw, K, dyn, Cs, 136);
    int tid = threadIdx.x;
    for (int e = tid; e < 4096; e += 256) {
        int r = e >> 5, c4 = (e & 31) * 4;
        float4 v = *(const float4*)(Cs + r * 136 + c4);
        if (bias) {
            float4 bv = *(const float4*)(bias + n0 + c4);
            v.x += bv.x; v.y += bv.y; v.z += bv.z; v.w += bv.w;
        }
        if (addW) {
            const bf16* aw = addW + (size_t)(m0 + r) * ldadd + n0 + c4;
            v.x += __bfloat162float(aw[0]); v.y += __bfloat162float(aw[1]);
            v.z += __bfloat162float(aw[2]); v.w += __bfloat162float(aw[3]);
        }
        bf162* o = (bf162*)(out + (size_t)(m0 + r) * ldo + n0 + c4);
        o[0] = cvt2(v.x, v.y); o[1] = cvt2(v.z, v.w);
    }
}

// ---------------- 128-tile vocab GEMM + fused LSE chunk ----------------
__global__ __launch_bounds__(256) void k_vocab128(const float* __restrict__ bias) {
    extern __shared__ __align__(16) char dyn[];
    float* Cs = (float*)dyn;
    int m0 = blockIdx.x * 128, n0 = blockIdx.y * 128;
    gemm128(g_avallb + (size_t)m0 * DDH, DDH, g_Wout + (size_t)n0 * DDH, DDH, DDH,
            dyn, Cs, 136);
    int tid = threadIdx.x;
    for (int e = tid; e < 4096; e += 256) {
        int r = e >> 5, c4 = (e & 31) * 4;
        float4 v = *(const float4*)(Cs + r * 136 + c4);
        float4 bv = *(const float4*)(bias + n0 + c4);
        v.x += bv.x; v.y += bv.y; v.z += bv.z; v.w += bv.w;
        *(float4*)(Cs + r * 136 + c4) = v;
    }
    __syncthreads();
    int row = tid >> 1, half = tid & 1;
    int rg = m0 + row;
    const float* Cr = Cs + row * 136 + half * 64;
    float m = -1e30f;
#pragma unroll 8
    for (int c = 0; c < 64; c++) m = fmaxf(m, Cr[c]);
    float mo = __shfl_xor_sync(0xffffffffu, m, 1);
    float mn = fmaxf(m, mo);
    float s = 0.f;
#pragma unroll 8
    for (int c = 0; c < 64; c++) s += __expf(Cr[c] - mn);
    s += __shfl_xor_sync(0xffffffffu, s, 1);
    if (rg < MR) {
        if (half == 0) {
            size_t co = ((size_t)rg * NTV + blockIdx.y) * 2;
            g_chunk[co + 0] = mn;
            g_chunk[co + 1] = s;
        }
        int loc = g_goldtok[rg] - n0 - half * 64;
        if (loc >= 0 && loc < 64) g_gold[rg] = Cr[loc];
    }
}

// ---------------- persistent encoder (32 blocks) + GEMM workers (116 blocks) ----------------
// Worker tile queue (all independent of encoder output):
//   id <  1024 : dec input projection  Gdec[m0:,n0:] = tvb @ WdecE^T + bdecP  (K=512, fp32 out)
//   id < 1280  : Wgate = WdecR[:, :1024] @ WhidLT^T + WdecR[:, 1024:]         (K=1024, bf16 out)
//   id < 1536  : WcombC = WdecR[:, :1024] @ WhidRT^T                          (K=1024, bf16 out)
// then out_W -> bf16 conversion, strided across worker blocks.
__global__ __launch_bounds__(256, 2) void k_enc_persist(
    const bf16* __restrict__ Wf, const bf16* __restrict__ Wr,
    const float* __restrict__ out_W)
{
    extern __shared__ __align__(16) char dyn[];
    float* Cs = (float*)dyn;
    int p = blockIdx.x, tid = threadIdx.x;
    if (p < NBE) {
        unsigned gen = 0;
        int d = p >> 4;
        int n0 = (p & 15) * 128;
        const bf16* A = g_hsb + d * (BB * HH);
        const bf16* W = (d ? Wr : Wf) + (size_t)n0 * HH;
        const float* pre_base = d ? g_Gr : g_Gf;
        for (int t = 0; t < TSR; t++) {
            gemm_core(A, HH, W, HH, HH, dyn, Cs, 136);
            for (int it = tid; it < 2048; it += 256) {
                int b = it >> 5, jl = it & 31;
                const float* cr = Cs + b * 136 + 4 * jl;
                const float* pre = pre_base + (size_t)(b * TSR + t) * 2048 + n0 + 4 * jl;
                float gi = cr[0] + pre[0];
                float gf = cr[1] + pre[1];
                float gg = cr[2] + pre[2];
                float go = cr[3] + pre[3];
                int j = (n0 >> 2) + jl;
                int si = d * (BB * HH) + (b << 9) + j;
                float c = sigf(gf) * g_cs[si] + sigf(gi) * tanhf(gg);
                float h = sigf(go) * tanhf(c);
                g_cs[si] = c;
                g_hsb[si] = __float2bfloat16(h);
                size_t o = (size_t)(b * TSR + t) * 1024 + d * 512 + j;
                g_Henc[o] = h; g_Cenc[o] = c; g_Hencb[o] = __float2bfloat16(h);
            }
            gsync(0, NBE, gen);
        }
    } else {
        // ---- worker path ----
        const int NW = NBENC - NBE;     // 116 workers
        for (int id = p - NBE; id < 1536; id += NW) {
            if (id < 1024) {
                int m0 = (id >> 5) * 128, n0 = (id & 31) * 128;
                gemm128(g_tvb + (size_t)m0 * EE, EE,
                        g_WdecE + (size_t)n0 * EE, EE, EE, dyn, Cs, 136);
                for (int e = tid; e < 4096; e += 256) {
                    int r = e >> 5, c4 = (e & 31) * 4;
                    float4 v = *(const float4*)(Cs + r * 136 + c4);
                    float4 bv = *(const float4*)(g_bdecP + n0 + c4);
                    v.x += bv.x; v.y += bv.y; v.z += bv.z; v.w += bv.w;
                    *(float4*)(g_Gdec + (size_t)(m0 + r) * 4096 + n0 + c4) = v;
                }
                __syncthreads();
            } else if (id < 1280) {
                int i2 = id - 1024;
                int m0 = (i2 >> 3) * 128, n0 = (i2 & 7) * 128;
                gemm128(g_WdecR + (size_t)m0 * 2048, 2048,
                        g_WhidLT + (size_t)n0 * 1024, 1024, 1024, dyn, Cs, 136);
                for (int e = tid; e < 4096; e += 256) {
                    int r = e >> 5, c4 = (e & 31) * 4;
                    float4 v = *(const float4*)(Cs + r * 136 + c4);
                    const bf16* aw = g_WdecR + (size_t)(m0 + r) * 2048 + 1024 + n0 + c4;
                    v.x += __bfloat162float(aw[0]); v.y += __bfloat162float(aw[1]);
                    v.z += __bfloat162float(aw[2]); v.w += __bfloat162float(aw[3]);
                    bf162* o = (bf162*)(g_Wgate + (size_t)(m0 + r) * 1024 + n0 + c4);
                    o[0] = cvt2(v.x, v.y); o[1] = cvt2(v.z, v.w);
                }
                __syncthreads();
            } else {
                int i2 = id - 1280;
                int m0 = (i2 >> 3) * 128, n0 = (i2 & 7) * 128;
                gemm128(g_WdecR + (size_t)m0 * 2048, 2048,
                        g_WhidRT + (size_t)n0 * 1024, 1024, 1024, dyn, Cs, 136);
                for (int e = tid; e < 4096; e += 256) {
                    int r = e >> 5, c4 = (e & 31) * 4;
                    float4 v = *(const float4*)(Cs + r * 136 + c4);
                    bf162* o = (bf162*)(g_WcombC + (size_t)(m0 + r) * 1024 + n0 + c4);
                    o[0] = cvt2(v.x, v.y); o[1] = cvt2(v.z, v.w);
                }
                __syncthreads();
            }
        }
        // out_W -> bf16, strided across workers
        const int n4 = VOC * DDH / 4;
        for (int i = (p - NBE) * 256 + tid; i < n4; i += (NBENC - NBE) * 256) {
            float4 v = ((const float4*)out_W)[i];
            ((bf162*)g_Wout)[2 * i]     = cvt2(v.x, v.y);
            ((bf162*)g_Wout)[2 * i + 1] = cvt2(v.z, v.w);
        }
    }
}

// ---------------- persistent decoder: 63 steps, 2 phases/step ----------------
__global__ __launch_bounds__(256, 2) void k_dec_persist(const int* __restrict__ src_lens) {
    extern __shared__ __align__(16) char dyn[];
    float* Cs = (float*)dyn;
    unsigned gen = 0;
    int p = blockIdx.x, tid = threadIdx.x;
    for (int t = 0; t < TD; t++) {
        // ---- Phase A ----
        if (p < 128) {
            int nt = p & 31, ks = p >> 5;
            const bf16* A = g_hb + ks * 256;
            const bf16* W; int ldw;
            if (t == 0) { W = g_WdecR + (size_t)(nt * 128) * 2048 + 1024 + ks * 256; ldw = 2048; }
            else        { W = g_Wgate + (size_t)(nt * 128) * 1024 + ks * 256; ldw = 1024; }
            gemm_core(A, 1024, W, ldw, 256, dyn,
                      g_Pg + (size_t)ks * (64 * 4096) + nt * 128, 4096);
        } else if (t > 0) {
            int q = p - 128, b = q >> 1;
            float* sps = Cs;                         // 64 floats
            if (tid < 64) sps[tid] = g_spg[b * 64 + tid];
            __syncthreads();
            int c0 = (q & 1) * 2048 + tid * 8;
            float acc[8];
#pragma unroll
            for (int i = 0; i < 8; i++) acc[i] = 0.f;
            const bf16* Hc0 = g_HencC + (size_t)(b * 64) * 4096 + c0;
            for (int u = 0; u < 64; u++) {
                float pw = sps[u];
                float4 r0 = *(const float4*)(Hc0 + (size_t)u * 4096);
                const bf162* pp = (const bf162*)&r0;
#pragma unroll
                for (int i = 0; i < 4; i++) {
                    float2 f = __bfloat1622float2(pp[i]);
                    acc[2 * i] += pw * f.x; acc[2 * i + 1] += pw * f.y;
                }
            }
            float* cgw = g_ctxg + (size_t)b * 4096 + c0;
            *(float4*)cgw       = make_float4(acc[0], acc[1], acc[2], acc[3]);
            *(float4*)(cgw + 4) = make_float4(acc[4], acc[5], acc[6], acc[7]);
            __syncthreads();
        }
        gsync(4, NBD, gen);
        // ---- Phase B ----
        if (p < 64) {
            int b = p;
            float* sh = Cs;            // 1024
            float* sc = Cs + 1024;     // 64
            float* sp = Cs + 1088;     // 64
            const float* pre = g_Gdec + (size_t)((t << 6) + b) * 4096;
            const float* P0 = g_Pg + (size_t)b * 4096;
            const float* cg = g_ctxg + (size_t)b * 4096;
#pragma unroll
            for (int u = 0; u < 4; u++) {
                int j = tid + u * 256;
                int col = 4 * j;
                float4 gp = *(const float4*)(pre + col);
                float4 q0 = *(const float4*)(P0 + col);
                float4 q1 = *(const float4*)(P0 + 64 * 4096 + col);
                float4 q2 = *(const float4*)(P0 + 2 * 64 * 4096 + col);
                float4 q3 = *(const float4*)(P0 + 3 * 64 * 4096 + col);
                float gi = gp.x + q0.x + q1.x + q2.x + q3.x;
                float gf = gp.y + q0.y + q1.y + q2.y + q3.y;
                float gg = gp.z + q0.z + q1.z + q2.z + q3.z;
                float go = gp.w + q0.w + q1.w + q2.w + q3.w;
                if (t > 0) {
                    float4 ca = *(const float4*)(g_constA + col);
                    float4 cx = *(const float4*)(cg + col);
                    gi += ca.x + cx.x; gf += ca.y + cx.y;
                    gg += ca.z + cx.z; go += ca.w + cx.w;
                }
                int ci = (b << 10) + j;
                float c = sigf(gf) * g_c[ci] + sigf(gi) * tanhf(gg);
                float h = sigf(go) * tanhf(c);
                g_c[ci] = c;
                sh[j] = h;
                bf16 hb = __float2bfloat16(h);
                g_hb[ci] = hb;
                g_yall[(size_t)((t << 6) + b) * 2048 + j] = hb;
            }
            __syncthreads();
            // attention scores
            {
                int tt = tid >> 2, q = tid & 3;
                const bf162* He = (const bf162*)(g_Hencb + (size_t)(b * TSR + tt) * 1024 + q * 256);
                const float* hh = sh + q * 256;
                float s = 0.f;
#pragma unroll 8
                for (int j = 0; j < 128; j++) {
                    bf162 v = He[j];
                    s += hh[2 * j] * __bfloat162float(v.x) + hh[2 * j + 1] * __bfloat162float(v.y);
                }
                s += __shfl_xor_sync(0xffffffffu, s, 1);
                s += __shfl_xor_sync(0xffffffffu, s, 2);
                if (q == 0) sc[tt] = s;
            }
            __syncthreads();
            int L = src_lens[b];
            float m = -1e30f;
            for (int u = 0; u < 64; u++) if (u < L) m = fmaxf(m, sc[u]);
            float den = 0.f;
            for (int u = 0; u < 64; u++) if (u < L) den += __expf(sc[u] - m);
            if (tid < 64) {
                float pv = (tid < L) ? (__expf(sc[tid] - m) / den) : 0.f;
                sp[tid] = pv;
                g_spg[b * 64 + tid] = pv;
            }
            __syncthreads();
            // ctx (1024) -> yall[..., 1024:2048]
            {
                int j0 = tid * 4;
                float a0 = 0.f, a1 = 0.f, a2 = 0.f, a3 = 0.f;
                for (int u = 0; u < L; u++) {
                    float pw = sp[u];
                    const bf162* Hr = (const bf162*)(g_Hencb + (size_t)(b * TSR + u) * 1024 + j0);
                    bf162 v0 = Hr[0], v1 = Hr[1];
                    a0 += pw * __bfloat162float(v0.x); a1 += pw * __bfloat162float(v0.y);
                    a2 += pw * __bfloat162float(v1.x); a3 += pw * __bfloat162float(v1.y);
                }
                bf162* co = (bf162*)(g_yall + (size_t)((t << 6) + b) * 2048 + 1024 + j0);
                co[0] = cvt2(a0, a1); co[1] = cvt2(a2, a3);
            }
        }
        gsync(4, NBD, gen);
    }
}

// ---------------- decoder init (fp32 path, one-time) ----------------
__global__ void k_final(const int* __restrict__ src_lens) {
    int i = blockIdx.x * blockDim.x + threadIdx.x;    // < 64*2048
    int b = i >> 11, j = i & 2047;
    int last = src_lens[b] - 1;
    size_t o = (size_t)(b * TSR + last) * 1024;
    g_final[i] = (j < 1024) ? g_Henc[o + j] : g_Cenc[o + j - 1024];
}

__global__ void k_sgemm_init(const float* __restrict__ W) {
    __shared__ float As[16][64];
    __shared__ float Ws[16][32];
    int z = blockIdx.z;
    int koff = z * 512;
    int tid = threadIdx.x;
    int n0 = blockIdx.x * 32;
    int ty = tid >> 3, tx = tid & 7;
    int lr = tid >> 1, lc = (tid & 1) * 8;
    int wr = tid >> 2, wc = (tid & 3) * 4;
    float acc[4][4];
#pragma unroll
    for (int i = 0; i < 4; i++)
#pragma unroll
        for (int j = 0; j < 4; j++) acc[i][j] = 0.f;
    const float* Ab = g_final + (size_t)lr * 2048 + koff + lc;
    const float* Wb = W + (size_t)(n0 + wr) * 2048 + koff + wc;
    for (int k0 = 0; k0 < 512; k0 += 16) {
        float4 a0 = *(const float4*)(Ab + k0);
        float4 a1 = *(const float4*)(Ab + k0 + 4);
        float4 b0 = *(const float4*)(Wb + k0);
        __syncthreads();
        As[lc + 0][lr] = a0.x; As[lc + 1][lr] = a0.y; As[lc + 2][lr] = a0.z; As[lc + 3][lr] = a0.w;
        As[lc + 4][lr] = a1.x; As[lc + 5][lr] = a1.y; As[lc + 6][lr] = a1.z; As[lc + 7][lr] = a1.w;
        Ws[wc + 0][wr] = b0.x; Ws[wc + 1][wr] = b0.y; Ws[wc + 2][wr] = b0.z; Ws[wc + 3][wr] = b0.w;
        __syncthreads();
#pragma unroll
        for (int kk = 0; kk < 16; kk++) {
            float a[4], b[4];
#pragma unroll
            for (int i = 0; i < 4; i++) a[i] = As[kk][ty * 4 + i];
#pragma unroll
            for (int j = 0; j < 4; j++) b[j] = Ws[kk][tx * 4 + j];
#pragma unroll
            for (int i = 0; i < 4; i++)
#pragma unroll
                for (int j = 0; j < 4; j++) acc[i][j] += a[i] * b[j];
        }
    }
    float* Pz = g_Phid + (size_t)z * (BB * DDH);
#pragma unroll
    for (int i = 0; i < 4; i++)
#pragma unroll
        for (int j = 0; j < 4; j++)
            Pz[(ty * 4 + i) * DDH + n0 + tx * 4 + j] = acc[i][j];
}

__global__ void k_init(const float* __restrict__ init_b) {
    int i = blockIdx.x * blockDim.x + threadIdx.x;    // < 64*1024
    int j = i & 1023;
    float c = init_b[j];
#pragma unroll
    for (int s = 0; s < 4; s++) c += g_Phid[s * (BB * DDH) + i];
    g_c[i] = c;
    g_hb[i] = __float2bfloat16(tanhf(c));
}

// ---------------- per-row LSE combine + masked sum ----------------
__global__ void k_rowlse() {
    int tid = threadIdx.x;                 // 256
    int b = tid >> 2, q = tid & 3;
    int row = blockIdx.x * 64 + b;
    const float* ch = g_chunk + (size_t)row * NTV * 2;
    float m = -1e30f;
    for (int i = q; i < NTV; i += 4) m = fmaxf(m, ch[2 * i]);
    m = fmaxf(m, __shfl_xor_sync(0xffffffffu, m, 1));
    m = fmaxf(m, __shfl_xor_sync(0xffffffffu, m, 2));
    float s = 0.f;
    for (int i = q; i < NTV; i += 4) s += ch[2 * i + 1] * __expf(ch[2 * i] - m);
    s += __shfl_xor_sync(0xffffffffu, s, 1);
    s += __shfl_xor_sync(0xffffffffu, s, 2);
    if (q == 0) {
        float lse = m + logf(s);
        g_rowval[row] = (g_gold[row] - lse) * g_maskf[row];
    }
}

__global__ void k_sum(float* __restrict__ out) {
    __shared__ float sm[256];
    int tid = threadIdx.x;
    float s = 0.f;
    for (int i = tid; i < MR; i += 256) s += g_rowval[i];
    sm[tid] = s;
    __syncthreads();
    for (int st = 128; st > 0; st >>= 1) {
        if (tid < st) sm[tid] += sm[tid + st];
        __syncthreads();
    }
    if (tid == 0) out[0] = sm[0];
}

// ---------------- launch ----------------
extern "C" void kernel_launch(void* const* d_in, const int* in_sizes, int n_in,
                              void* d_out, int out_size) {
    (void)in_sizes; (void)n_in; (void)out_size;
    const int*   src_tokens = (const int*)d_in[0];
    const int*   src_lens   = (const int*)d_in[1];
    const int*   trg_tokens = (const int*)d_in[2];
    const int*   trg_lens   = (const int*)d_in[3];
    const float* src_emb    = (const float*)d_in[4];
    const float* trg_emb    = (const float*)d_in[5];
    const float* enc_Wih    = (const float*)d_in[6];
    const float* enc_Whh    = (const float*)d_in[7];
    const float* enc_b      = (const float*)d_in[8];
    const float* rev_Wih    = (const float*)d_in[9];
    const float* rev_Whh    = (const float*)d_in[10];
    const float* rev_b      = (const float*)d_in[11];
    const float* dec_Wih    = (const float*)d_in[12];
    const float* dec_Whh    = (const float*)d_in[13];
    const float* dec_b      = (const float*)d_in[14];
    const float* hid_W      = (const float*)d_in[15];
    const float* hid_b      = (const float*)d_in[16];
    const float* out_W      = (const float*)d_in[17];
    const float* out_b      = (const float*)d_in[18];
    const float* init_W     = (const float*)d_in[19];
    const float* init_b     = (const float*)d_in[20];

    bf16 *p_svb, *p_tvb, *p_Wencf, *p_Wencr, *p_Whhf, *p_Whhr, *p_WdecE, *p_WhidB,
         *p_Wout, *p_WhidLT, *p_WhidRT, *p_Wgate, *p_WcombC, *p_HencC, *p_Hencb,
         *p_WdecR, *p_yall, *p_avallb;
    float *p_Gf, *p_Gr, *p_Gdec, *p_bencf, *p_bencr, *p_bdec;
    cudaGetSymbolAddress((void**)&p_svb, g_svb);
    cudaGetSymbolAddress((void**)&p_tvb, g_tvb);
    cudaGetSymbolAddress((void**)&p_Wencf, g_WencfP);
    cudaGetSymbolAddress((void**)&p_Wencr, g_WencrP);
    cudaGetSymbolAddress((void**)&p_Whhf, g_WhhfP);
    cudaGetSymbolAddress((void**)&p_Whhr, g_WhhrP);
    cudaGetSymbolAddress((void**)&p_WdecE, g_WdecE);
    cudaGetSymbolAddress((void**)&p_WhidB, g_WhidB);
    cudaGetSymbolAddress((void**)&p_Wout, g_Wout);
    cudaGetSymbolAddress((void**)&p_WhidLT, g_WhidLT);
    cudaGetSymbolAddress((void**)&p_WhidRT, g_WhidRT);
    cudaGetSymbolAddress((void**)&p_Wgate, g_Wgate);
    cudaGetSymbolAddress((void**)&p_WcombC, g_WcombC);
    cudaGetSymbolAddress((void**)&p_HencC, g_HencC);
    cudaGetSymbolAddress((void**)&p_Hencb, g_Hencb);
    cudaGetSymbolAddress((void**)&p_WdecR, g_WdecR);
    cudaGetSymbolAddress((void**)&p_yall, g_yall);
    cudaGetSymbolAddress((void**)&p_avallb, g_avallb);
    cudaGetSymbolAddress((void**)&p_Gf, g_Gf);
    cudaGetSymbolAddress((void**)&p_Gr, g_Gr);
    cudaGetSymbolAddress((void**)&p_Gdec, g_Gdec);
    cudaGetSymbolAddress((void**)&p_bencf, g_bencfP);
    cudaGetSymbolAddress((void**)&p_bencr, g_bencrP);
    cudaGetSymbolAddress((void**)&p_bdec, g_bdecP);

    // dynamic smem opt-in
    cudaFuncSetAttribute(k_ff128, cudaFuncAttributeMaxDynamicSharedMemorySize, DYN2);
    cudaFuncSetAttribute(k_gemm128_b, cudaFuncAttributeMaxDynamicSharedMemorySize, DYN2);
    cudaFuncSetAttribute(k_vocab128, cudaFuncAttributeMaxDynamicSharedMemorySize, DYN2);
    cudaFuncSetAttribute(k_enc_persist, cudaFuncAttributeMaxDynamicSharedMemorySize, DYN2);
    cudaFuncSetAttribute(k_dec_persist, cudaFuncAttributeMaxDynamicSharedMemorySize, DYN_SMEM);

    k_zero_state<<<256, 256>>>();
    k_zeropad<<<512, 256>>>();
    k_gather_src<<<BB * TSR, 128>>>(src_tokens, src_emb);
    k_gather_trg<<<MR, 128>>>(trg_tokens, trg_lens, trg_emb);

    // weight conversions + gate-interleave permutations
    k_permW512<<<2048, 128>>>(enc_Wih, p_Wencf, 512, 512);
    k_permW512<<<2048, 128>>>(rev_Wih, p_Wencr, 512, 512);
    k_permW512<<<2048, 128>>>(enc_Whh, p_Whhf, 512, 512);
    k_permW512<<<2048, 128>>>(rev_Whh, p_Whhr, 512, 512);
    k_permW512<<<4096, 128>>>(dec_Wih, p_WdecE, 1024, 1536);
    k_permDecR<<<4096, 256>>>(dec_Wih, dec_Whh);
    k_permB<<<8, 256>>>(enc_b, p_bencf, 512);
    k_permB<<<8, 256>>>(rev_b, p_bencr, 512);
    k_permB<<<16, 256>>>(dec_b, p_bdec, 1024);
    k_f2b<<<(DDH * 2048 / 4 + 255) / 256, 256>>>(hid_W, p_WhidB, DDH * 2048 / 4);
    k_transpose_hid<<<dim3(32, 32, 2), dim3(32, 8)>>>(hid_W);
    k_const<<<512, 256>>>(hid_b);

    // encoder input projections (must complete before the encoder recurrence)
    k_ff128<<<dim3(32, 16), 256, DYN2>>>(p_svb, EE, p_Wencf, EE, p_bencf, p_Gf, 2048, EE);
    k_ff128<<<dim3(32, 16), 256, DYN2>>>(p_svb, EE, p_Wencr, EE, p_bencr, p_Gr, 2048, EE);

    // encoder recurrence (32 blocks) + workers: dec input projection, Wgate, WcombC,
    // out_W conversion — all run on the otherwise-idle 116 SMs.
    k_enc_persist<<<NBENC, 256, DYN2>>>(p_Whhf, p_Whhr, out_W);

    // HencC = Henc @ WcombC^T  (needs encoder output + WcombC, both done above)
    k_gemm128_b<<<dim3(32, 32), 256, DYN2>>>(p_Hencb, 1024, p_WcombC, 1024, 1024,
                                             (const float*)0, (const bf16*)0, 0,
                                             p_HencC, 4096);

    // decoder init state
    k_final<<<512, 256>>>(src_lens);
    k_sgemm_init<<<dim3(32, 1, 4), 128>>>(init_W);
    k_init<<<256, 256>>>(init_b);

    // decoder recurrence (persistent, 2 phases/step)
    k_dec_persist<<<NBD, 256, DYN_SMEM>>>(src_lens);

    // deferred hid GEMM: avall = [h|ctx] @ hid_W^T + hid_b
    k_gemm128_b<<<dim3(32, 8), 256, DYN2>>>(p_yall, 2048, p_WhidB, 2048, 2048,
                                            hid_b, (const bf16*)0, 0, p_avallb, 1024);

    // vocab projection + LSE (128-tile)
    k_vocab128<<<dim3(32, NTV), 256, DYN2>>>(out_b);
    k_rowlse<<<63, 256>>>();
    k_sum<<<1, 256>>>((float*)d_out);
}